// round 5
// baseline (speedup 1.0000x reference)
#include <cuda_runtime.h>
#include <mma.h>
#include <math.h>

using namespace nvcuda;

#define DIM    2048
#define SEQ    2048
#define BATCH  2
#define HEADS  16
#define HDIM   128
#define MROWS  (BATCH*SEQ)   /* 4096 */

// ---------------- scratch (device globals; no allocations) ----------------
__device__ float g_q[(size_t)MROWS * DIM];
__device__ float g_k[(size_t)MROWS * DIM];
__device__ float g_v[(size_t)MROWS * DIM];
__device__ float g_attn[(size_t)MROWS * DIM];

// ============================================================================
// NT GEMM: C[M,N] = A[M,K] @ B[N,K]^T   (tf32 wmma, fp32 accumulate)
// Block tile 128x128, K-tile 32, 256 threads (8 warps, 2x4), warp tile 64x32.
// ============================================================================
__global__ __launch_bounds__(256) void gemm_nt_tf32(
    const float* __restrict__ A, const float* __restrict__ B,
    float* __restrict__ C, int M, int N, int K)
{
    __shared__ float As[128][36];
    __shared__ float Bs[128][36];

    const int bm = blockIdx.y * 128;
    const int bn = blockIdx.x * 128;
    const int tid  = threadIdx.x;
    const int warp = tid >> 5;
    const int wm = warp >> 2;     // 0..1
    const int wn = warp & 3;      // 0..3

    wmma::fragment<wmma::accumulator, 16, 16, 8, float> acc[4][2];
#pragma unroll
    for (int i = 0; i < 4; i++)
#pragma unroll
        for (int j = 0; j < 2; j++)
            wmma::fill_fragment(acc[i][j], 0.0f);

    for (int k0 = 0; k0 < K; k0 += 32) {
#pragma unroll
        for (int i = 0; i < 4; i++) {
            int idx = tid + i * 256;          // 0..1023 float4 slots
            int r = idx >> 3;
            int c = (idx & 7) << 2;
            *(float4*)&As[r][c] = *(const float4*)&A[(size_t)(bm + r) * K + k0 + c];
            *(float4*)&Bs[r][c] = *(const float4*)&B[(size_t)(bn + r) * K + k0 + c];
        }
        __syncthreads();

#pragma unroll
        for (int kk = 0; kk < 32; kk += 8) {
            wmma::fragment<wmma::matrix_a, 16, 16, 8, wmma::precision::tf32, wmma::row_major> af[4];
            wmma::fragment<wmma::matrix_b, 16, 16, 8, wmma::precision::tf32, wmma::col_major> bf[2];
#pragma unroll
            for (int i = 0; i < 4; i++) {
                wmma::load_matrix_sync(af[i], &As[wm * 64 + i * 16][kk], 36);
#pragma unroll
                for (int t = 0; t < af[i].num_elements; t++)
                    af[i].x[t] = wmma::__float_to_tf32(af[i].x[t]);
            }
#pragma unroll
            for (int j = 0; j < 2; j++) {
                wmma::load_matrix_sync(bf[j], &Bs[wn * 32 + j * 16][kk], 36);
#pragma unroll
                for (int t = 0; t < bf[j].num_elements; t++)
                    bf[j].x[t] = wmma::__float_to_tf32(bf[j].x[t]);
            }
#pragma unroll
            for (int i = 0; i < 4; i++)
#pragma unroll
                for (int j = 0; j < 2; j++)
                    wmma::mma_sync(acc[i][j], af[i], bf[j], acc[i][j]);
        }
        __syncthreads();
    }

#pragma unroll
    for (int i = 0; i < 4; i++)
#pragma unroll
        for (int j = 0; j < 2; j++) {
            size_t r = bm + wm * 64 + i * 16;
            size_t c = bn + wn * 32 + j * 16;
            wmma::store_matrix_sync(&C[r * N + c], acc[i][j], N, wmma::mem_row_major);
        }
}

// ============================================================================
// Fused RMSNorm (over full dim=2048) + interleaved RoPE, in-place on q or k.
// grid: (MROWS, 2)  y==0 -> q/gq, y==1 -> k/gk.  256 threads per row.
// ============================================================================
__global__ __launch_bounds__(256) void rmsnorm_rope_kernel(
    float* __restrict__ q, float* __restrict__ k,
    const float* __restrict__ gq, const float* __restrict__ gk,
    const float* __restrict__ freqs)
{
    float* x = (blockIdx.y == 0) ? q : k;
    const float* g = (blockIdx.y == 0) ? gq : gk;
    const int row = blockIdx.x;          // 0..4095
    const int s   = row & (SEQ - 1);
    float* xr = x + (size_t)row * DIM;
    const int tid = threadIdx.x;

    float4 a = ((const float4*)xr)[tid];        // elems 4*tid .. 4*tid+3
    float4 b = ((const float4*)xr)[tid + 256];  // elems 1024+4*tid ..

    float ss = a.x*a.x + a.y*a.y + a.z*a.z + a.w*a.w
             + b.x*b.x + b.y*b.y + b.z*b.z + b.w*b.w;
#pragma unroll
    for (int o = 16; o > 0; o >>= 1)
        ss += __shfl_xor_sync(0xffffffffu, ss, o);

    __shared__ float red[8];
    if ((tid & 31) == 0) red[tid >> 5] = ss;
    __syncthreads();
    float tot = 0.f;
#pragma unroll
    for (int w = 0; w < 8; w++) tot += red[w];

    const float inv = rsqrtf(tot * (1.0f / (float)DIM) + 1e-6f);

    float4 ga = ((const float4*)g)[tid];
    float4 gb = ((const float4*)g)[tid + 256];
    const float* fr = freqs + (size_t)s * (HDIM / 2);

    // first float4: pairs p0 = 2*tid, p1 = 2*tid+1  (pair-in-head = p & 63)
    {
        int p0 = 2 * tid, p1 = 2 * tid + 1;
        float s0, c0, s1, c1;
        sincosf(fr[p0 & 63], &s0, &c0);
        sincosf(fr[p1 & 63], &s1, &c1);
        float v0 = a.x * inv * ga.x, v1 = a.y * inv * ga.y;
        float v2 = a.z * inv * ga.z, v3 = a.w * inv * ga.w;
        float4 o;
        o.x = v0 * c0 - v1 * s0;  o.y = v0 * s0 + v1 * c0;
        o.z = v2 * c1 - v3 * s1;  o.w = v2 * s1 + v3 * c1;
        ((float4*)xr)[tid] = o;
    }
    // second float4: pairs 512+2*tid, 513+2*tid
    {
        int p0 = 512 + 2 * tid, p1 = 513 + 2 * tid;
        float s0, c0, s1, c1;
        sincosf(fr[p0 & 63], &s0, &c0);
        sincosf(fr[p1 & 63], &s1, &c1);
        float v0 = b.x * inv * gb.x, v1 = b.y * inv * gb.y;
        float v2 = b.z * inv * gb.z, v3 = b.w * inv * gb.w;
        float4 o;
        o.x = v0 * c0 - v1 * s0;  o.y = v0 * s0 + v1 * c0;
        o.z = v2 * c1 - v3 * s1;  o.w = v2 * s1 + v3 * c1;
        ((float4*)xr)[tid + 256] = o;
    }
}

// ============================================================================
// Flash attention (varlen key mask). One CTA = (batch, head, 64-query tile).
// kv tiles of 64 keys; invalid tiles skipped exactly (exp underflow).
// smem layout (floats):
//   Qs 64x132 | Ks 64x132 | Vs 64x132 | Ss 64x68 | Os 64x132 | Ts 64x132 | m/l/rs
// ============================================================================
#define SM_QS 0
#define SM_KS 8448
#define SM_VS 16896
#define SM_SS 25344
#define SM_OS 29696
#define SM_TS 38144
#define SM_M  46592
#define SM_L  46656
#define SM_RS 46720
#define ATTN_SMEM_FLOATS 46784
#define ATTN_SMEM_BYTES  (ATTN_SMEM_FLOATS * 4)

__global__ __launch_bounds__(256) void attn_kernel(const int* __restrict__ seq_lens)
{
    extern __shared__ float sm[];
    float* Qs = sm + SM_QS;
    float* Ks = sm + SM_KS;
    float* Vs = sm + SM_VS;
    float* Ss = sm + SM_SS;
    float* Os = sm + SM_OS;
    float* Ts = sm + SM_TS;
    float* mrow  = sm + SM_M;
    float* lrow  = sm + SM_L;
    float* rsrow = sm + SM_RS;

    const int b  = blockIdx.z;
    const int h  = blockIdx.y;
    const int q0 = blockIdx.x * 64;
    const int seqlen = seq_lens[b];
    const int tid  = threadIdx.x;
    const int warp = tid >> 5;
    const float scale = 0.08838834764831845f;   // 1/sqrt(128)

    // load Q tile, zero O, init m/l
#pragma unroll
    for (int i = 0; i < 8; i++) {
        int idx = tid + i * 256;               // 0..2047 float4 slots
        int r = idx >> 5, c4 = idx & 31;
        const float* src = g_q + ((size_t)(b * SEQ + q0 + r) * DIM + h * HDIM + c4 * 4);
        *(float4*)&Qs[r * 132 + c4 * 4] = *(const float4*)src;
        *(float4*)&Os[r * 132 + c4 * 4] = make_float4(0.f, 0.f, 0.f, 0.f);
    }
    if (tid < 64) { mrow[tid] = -1e30f; lrow[tid] = 0.f; }
    __syncthreads();

    for (int kv0 = 0; kv0 < seqlen; kv0 += 64) {
        // ---- load K/V tiles ----
#pragma unroll
        for (int i = 0; i < 8; i++) {
            int idx = tid + i * 256;
            int r = idx >> 5, c4 = idx & 31;
            size_t base = (size_t)(b * SEQ + kv0 + r) * DIM + h * HDIM + c4 * 4;
            *(float4*)&Ks[r * 132 + c4 * 4] = *(const float4*)(g_k + base);
            *(float4*)&Vs[r * 132 + c4 * 4] = *(const float4*)(g_v + base);
        }
        __syncthreads();

        // ---- S = scale * Q @ K^T  (64x64), warp grid 2x4 (32x16 per warp) ----
        {
            const int wm = warp >> 2, wn = warp & 3;
            wmma::fragment<wmma::accumulator, 16, 16, 8, float> acc[2];
#pragma unroll
            for (int i = 0; i < 2; i++) wmma::fill_fragment(acc[i], 0.f);
#pragma unroll
            for (int kk = 0; kk < HDIM; kk += 8) {
                wmma::fragment<wmma::matrix_a, 16, 16, 8, wmma::precision::tf32, wmma::row_major> af[2];
                wmma::fragment<wmma::matrix_b, 16, 16, 8, wmma::precision::tf32, wmma::col_major> bf;
#pragma unroll
                for (int i = 0; i < 2; i++) {
                    wmma::load_matrix_sync(af[i], &Qs[(wm * 32 + i * 16) * 132 + kk], 132);
#pragma unroll
                    for (int t = 0; t < af[i].num_elements; t++)
                        af[i].x[t] = wmma::__float_to_tf32(af[i].x[t]);
                }
                wmma::load_matrix_sync(bf, &Ks[(wn * 16) * 132 + kk], 132);
#pragma unroll
                for (int t = 0; t < bf.num_elements; t++)
                    bf.x[t] = wmma::__float_to_tf32(bf.x[t]);
#pragma unroll
                for (int i = 0; i < 2; i++)
                    wmma::mma_sync(acc[i], af[i], bf, acc[i]);
            }
#pragma unroll
            for (int i = 0; i < 2; i++) {
#pragma unroll
                for (int t = 0; t < acc[i].num_elements; t++) acc[i].x[t] *= scale;
                wmma::store_matrix_sync(&Ss[(wm * 32 + i * 16) * 68 + wn * 16],
                                        acc[i], 68, wmma::mem_row_major);
            }
        }
        __syncthreads();

        // ---- online softmax: 4 threads per row (16 cols each) ----
        {
            const int r = tid >> 2, sub = tid & 3;
            const int c0 = sub * 16;
            const int nvalid = seqlen - kv0;    // >= 1
            float vmax = -1e30f;
#pragma unroll
            for (int c = c0; c < c0 + 16; c++) {
                float v = Ss[r * 68 + c];
                if (c < nvalid) vmax = fmaxf(vmax, v);
            }
            vmax = fmaxf(vmax, __shfl_xor_sync(0xffffffffu, vmax, 1));
            vmax = fmaxf(vmax, __shfl_xor_sync(0xffffffffu, vmax, 2));
            const float mold = mrow[r];
            const float mnew = fmaxf(mold, vmax);
            float sum = 0.f;
#pragma unroll
            for (int c = c0; c < c0 + 16; c++) {
                float p = (c < nvalid) ? __expf(Ss[r * 68 + c] - mnew) : 0.f;
                Ss[r * 68 + c] = p;
                sum += p;
            }
            sum += __shfl_xor_sync(0xffffffffu, sum, 1);
            sum += __shfl_xor_sync(0xffffffffu, sum, 2);
            if (sub == 0) {
                float rsc = __expf(mold - mnew);
                lrow[r] = lrow[r] * rsc + sum;
                mrow[r] = mnew;
                rsrow[r] = rsc;
            }
        }
        __syncthreads();

        // ---- T = P @ V  (64x128), warp grid 2x4 (32x32 per warp) ----
        {
            const int wm = warp >> 2, wn = warp & 3;
            wmma::fragment<wmma::accumulator, 16, 16, 8, float> acc[2][2];
#pragma unroll
            for (int i = 0; i < 2; i++)
#pragma unroll
                for (int j = 0; j < 2; j++) wmma::fill_fragment(acc[i][j], 0.f);
#pragma unroll
            for (int kk = 0; kk < 64; kk += 8) {
                wmma::fragment<wmma::matrix_a, 16, 16, 8, wmma::precision::tf32, wmma::row_major> pf[2];
                wmma::fragment<wmma::matrix_b, 16, 16, 8, wmma::precision::tf32, wmma::row_major> vf[2];
#pragma unroll
                for (int i = 0; i < 2; i++) {
                    wmma::load_matrix_sync(pf[i], &Ss[(wm * 32 + i * 16) * 68 + kk], 68);
#pragma unroll
                    for (int t = 0; t < pf[i].num_elements; t++)
                        pf[i].x[t] = wmma::__float_to_tf32(pf[i].x[t]);
                }
#pragma unroll
                for (int j = 0; j < 2; j++) {
                    wmma::load_matrix_sync(vf[j], &Vs[kk * 132 + wn * 32 + j * 16], 132);
#pragma unroll
                    for (int t = 0; t < vf[j].num_elements; t++)
                        vf[j].x[t] = wmma::__float_to_tf32(vf[j].x[t]);
                }
#pragma unroll
                for (int i = 0; i < 2; i++)
#pragma unroll
                    for (int j = 0; j < 2; j++)
                        wmma::mma_sync(acc[i][j], pf[i], vf[j], acc[i][j]);
            }
#pragma unroll
            for (int i = 0; i < 2; i++)
#pragma unroll
                for (int j = 0; j < 2; j++)
                    wmma::store_matrix_sync(&Ts[(wm * 32 + i * 16) * 132 + wn * 32 + j * 16],
                                            acc[i][j], 132, wmma::mem_row_major);
        }
        __syncthreads();

        // ---- O = O * rs[row] + T ----
#pragma unroll
        for (int i = 0; i < 8; i++) {
            int idx = tid + i * 256;
            int r = idx >> 5, c4 = idx & 31;
            float rsc = rsrow[r];
            float4 o = *(float4*)&Os[r * 132 + c4 * 4];
            float4 t = *(float4*)&Ts[r * 132 + c4 * 4];
            o.x = o.x * rsc + t.x;  o.y = o.y * rsc + t.y;
            o.z = o.z * rsc + t.z;  o.w = o.w * rsc + t.w;
            *(float4*)&Os[r * 132 + c4 * 4] = o;
        }
        __syncthreads();
    }

    // ---- write attn = O / l ----
#pragma unroll
    for (int i = 0; i < 8; i++) {
        int idx = tid + i * 256;
        int r = idx >> 5, c4 = idx & 31;
        float invl = 1.0f / lrow[r];
        float4 o = *(float4*)&Os[r * 132 + c4 * 4];
        o.x *= invl; o.y *= invl; o.z *= invl; o.w *= invl;
        float* dst = g_attn + ((size_t)(b * SEQ + q0 + r) * DIM + h * HDIM + c4 * 4);
        *(float4*)dst = o;
    }
}

// ============================================================================
// bias add (bo is zeros in this dataset, applied anyway for fidelity)
// ============================================================================
__global__ __launch_bounds__(256) void bias_add_kernel(float* __restrict__ out,
                                                       const float* __restrict__ bo)
{
    size_t i = (size_t)blockIdx.x * blockDim.x + threadIdx.x;   // float4 index
    float4 v = ((float4*)out)[i];
    float4 b = ((const float4*)bo)[i & 511];                    // 2048 floats = 512 float4 / row
    v.x += b.x; v.y += b.y; v.z += b.z; v.w += b.w;
    ((float4*)out)[i] = v;
}

// ============================================================================
extern "C" void kernel_launch(void* const* d_in, const int* in_sizes, int n_in,
                              void* d_out, int out_size)
{
    const float* x        = (const float*)d_in[0];
    const int*   seq_lens = (const int*)d_in[1];
    /* d_in[2] grid_sizes (int64) — unused by reference */
    const float* freqs    = (const float*)d_in[3];
    const float* Wq       = (const float*)d_in[4];
    const float* Wk       = (const float*)d_in[5];
    const float* Wv       = (const float*)d_in[6];
    const float* Wo       = (const float*)d_in[7];
    const float* bo       = (const float*)d_in[8];
    const float* gq       = (const float*)d_in[9];
    const float* gk       = (const float*)d_in[10];
    float* out = (float*)d_out;

    cudaFuncSetAttribute(attn_kernel, cudaFuncAttributeMaxDynamicSharedMemorySize,
                         ATTN_SMEM_BYTES);

    float *pq, *pk, *pv, *pa;
    cudaGetSymbolAddress((void**)&pq, g_q);
    cudaGetSymbolAddress((void**)&pk, g_k);
    cudaGetSymbolAddress((void**)&pv, g_v);
    cudaGetSymbolAddress((void**)&pa, g_attn);

    dim3 ggrid(DIM / 128, MROWS / 128);   // (16, 32)

    gemm_nt_tf32<<<ggrid, 256>>>(x, Wq, pq, MROWS, DIM, DIM);
    gemm_nt_tf32<<<ggrid, 256>>>(x, Wk, pk, MROWS, DIM, DIM);
    gemm_nt_tf32<<<ggrid, 256>>>(x, Wv, pv, MROWS, DIM, DIM);

    rmsnorm_rope_kernel<<<dim3(MROWS, 2), 256>>>(pq, pk, gq, gk, freqs);

    attn_kernel<<<dim3(SEQ / 64, HEADS, BATCH), 256, ATTN_SMEM_BYTES>>>(seq_lens);

    gemm_nt_tf32<<<ggrid, 256>>>(pa, Wo, out, MROWS, DIM, DIM);
    bias_add_kernel<<<(MROWS * DIM / 4) / 256, 256>>>(out, bo);
}

// round 7
// speedup vs baseline: 1.1364x; 1.1364x over previous
#include <cuda_runtime.h>
#include <mma.h>
#include <math.h>

using namespace nvcuda;

#define DIM    2048
#define SEQ    2048
#define BATCH  2
#define HEADS  16
#define HDIM   128
#define MROWS  (BATCH*SEQ)   /* 4096 */

// ---------------- scratch (device globals; no allocations) ----------------
__device__ float g_q[(size_t)MROWS * DIM];
__device__ float g_k[(size_t)MROWS * DIM];
__device__ float g_v[(size_t)MROWS * DIM];
__device__ float g_attn[(size_t)MROWS * DIM];

// ---------------- cp.async helpers ----------------
__device__ __forceinline__ void cp_async16(void* dst, const void* src) {
    unsigned d = (unsigned)__cvta_generic_to_shared(dst);
    asm volatile("cp.async.cg.shared.global [%0], [%1], 16;\n" :: "r"(d), "l"(src));
}
#define CP_COMMIT() asm volatile("cp.async.commit_group;\n" ::: "memory")
#define CP_WAIT(n)  asm volatile("cp.async.wait_group %0;\n" :: "n"(n) : "memory")

// ============================================================================
// NT GEMM: C[M,N] = A[M,K] @ B[N,K]^T   (tf32 wmma, fp32 accumulate)
// 128x128 block tile, K-tile 32, 3-stage cp.async pipeline, 256 threads.
// ============================================================================
#define GSTG 3
#define GSTAGE_F (128*36)
#define GEMM_SMEM_BYTES (2 * GSTG * GSTAGE_F * 4)   /* 110592 */

__global__ __launch_bounds__(256) void gemm_nt_tf32(
    const float* __restrict__ A, const float* __restrict__ B,
    float* __restrict__ C, int M, int N, int K)
{
    extern __shared__ float sm[];
    float* As = sm;
    float* Bs = sm + GSTG * GSTAGE_F;

    const int bm = blockIdx.y * 128;
    const int bn = blockIdx.x * 128;
    const int tid  = threadIdx.x;
    const int warp = tid >> 5;
    const int wm = warp >> 2;     // 0..1
    const int wn = warp & 3;      // 0..3
    const int r0 = tid >> 3;            // 0..31
    const int c0 = (tid & 7) << 2;      // 0,4,..28

    const int ntiles = K / 32;

    wmma::fragment<wmma::accumulator, 16, 16, 8, float> acc[4][2];
#pragma unroll
    for (int i = 0; i < 4; i++)
#pragma unroll
        for (int j = 0; j < 2; j++)
            wmma::fill_fragment(acc[i][j], 0.0f);

    // issue tile t into stage t % GSTG
    auto issue_tile = [&](int t) {
        int s = t % GSTG;
        int k0 = t * 32;
        float* as = As + s * GSTAGE_F;
        float* bs = Bs + s * GSTAGE_F;
#pragma unroll
        for (int i = 0; i < 4; i++) {
            int r = r0 + 32 * i;
            cp_async16(&as[r * 36 + c0], &A[(size_t)(bm + r) * K + k0 + c0]);
            cp_async16(&bs[r * 36 + c0], &B[(size_t)(bn + r) * K + k0 + c0]);
        }
    };

    issue_tile(0); CP_COMMIT();
    issue_tile(1); CP_COMMIT();

    for (int t = 0; t < ntiles; t++) {
        CP_WAIT(GSTG - 2);          // tile t resident
        __syncthreads();            // (also protects stage about to be overwritten)
        if (t + 2 < ntiles) issue_tile(t + 2);
        CP_COMMIT();                // commit (possibly empty) to keep group counts aligned

        const float* as = As + (t % GSTG) * GSTAGE_F;
        const float* bs = Bs + (t % GSTG) * GSTAGE_F;

#pragma unroll
        for (int kk = 0; kk < 32; kk += 8) {
            wmma::fragment<wmma::matrix_a, 16, 16, 8, wmma::precision::tf32, wmma::row_major> af[4];
            wmma::fragment<wmma::matrix_b, 16, 16, 8, wmma::precision::tf32, wmma::col_major> bf[2];
#pragma unroll
            for (int i = 0; i < 4; i++) {
                wmma::load_matrix_sync(af[i], &as[(wm * 64 + i * 16) * 36 + kk], 36);
#pragma unroll
                for (int t2 = 0; t2 < af[i].num_elements; t2++)
                    af[i].x[t2] = wmma::__float_to_tf32(af[i].x[t2]);
            }
#pragma unroll
            for (int j = 0; j < 2; j++) {
                wmma::load_matrix_sync(bf[j], &bs[(wn * 32 + j * 16) * 36 + kk], 36);
#pragma unroll
                for (int t2 = 0; t2 < bf[j].num_elements; t2++)
                    bf[j].x[t2] = wmma::__float_to_tf32(bf[j].x[t2]);
            }
#pragma unroll
            for (int i = 0; i < 4; i++)
#pragma unroll
                for (int j = 0; j < 2; j++)
                    wmma::mma_sync(acc[i][j], af[i], bf[j], acc[i][j]);
        }
    }

#pragma unroll
    for (int i = 0; i < 4; i++)
#pragma unroll
        for (int j = 0; j < 2; j++) {
            size_t r = bm + wm * 64 + i * 16;
            size_t c = bn + wn * 32 + j * 16;
            wmma::store_matrix_sync(&C[r * N + c], acc[i][j], N, wmma::mem_row_major);
        }
}

// ============================================================================
// Fused RMSNorm (over full dim=2048) + interleaved RoPE, in-place on q or k.
// grid: (MROWS, 2)  y==0 -> q/gq, y==1 -> k/gk.  256 threads per row.
// ============================================================================
__global__ __launch_bounds__(256) void rmsnorm_rope_kernel(
    float* __restrict__ q, float* __restrict__ k,
    const float* __restrict__ gq, const float* __restrict__ gk,
    const float* __restrict__ freqs)
{
    float* x = (blockIdx.y == 0) ? q : k;
    const float* g = (blockIdx.y == 0) ? gq : gk;
    const int row = blockIdx.x;          // 0..4095
    const int s   = row & (SEQ - 1);
    float* xr = x + (size_t)row * DIM;
    const int tid = threadIdx.x;

    float4 a = ((const float4*)xr)[tid];
    float4 b = ((const float4*)xr)[tid + 256];

    float ss = a.x*a.x + a.y*a.y + a.z*a.z + a.w*a.w
             + b.x*b.x + b.y*b.y + b.z*b.z + b.w*b.w;
#pragma unroll
    for (int o = 16; o > 0; o >>= 1)
        ss += __shfl_xor_sync(0xffffffffu, ss, o);

    __shared__ float red[8];
    if ((tid & 31) == 0) red[tid >> 5] = ss;
    __syncthreads();
    float tot = 0.f;
#pragma unroll
    for (int w = 0; w < 8; w++) tot += red[w];

    const float inv = rsqrtf(tot * (1.0f / (float)DIM) + 1e-6f);

    float4 ga = ((const float4*)g)[tid];
    float4 gb = ((const float4*)g)[tid + 256];
    const float* fr = freqs + (size_t)s * (HDIM / 2);

    {
        int p0 = 2 * tid, p1 = 2 * tid + 1;
        float s0, c0, s1, c1;
        sincosf(fr[p0 & 63], &s0, &c0);
        sincosf(fr[p1 & 63], &s1, &c1);
        float v0 = a.x * inv * ga.x, v1 = a.y * inv * ga.y;
        float v2 = a.z * inv * ga.z, v3 = a.w * inv * ga.w;
        float4 o;
        o.x = v0 * c0 - v1 * s0;  o.y = v0 * s0 + v1 * c0;
        o.z = v2 * c1 - v3 * s1;  o.w = v2 * s1 + v3 * c1;
        ((float4*)xr)[tid] = o;
    }
    {
        int p0 = 512 + 2 * tid, p1 = 513 + 2 * tid;
        float s0, c0, s1, c1;
        sincosf(fr[p0 & 63], &s0, &c0);
        sincosf(fr[p1 & 63], &s1, &c1);
        float v0 = b.x * inv * gb.x, v1 = b.y * inv * gb.y;
        float v2 = b.z * inv * gb.z, v3 = b.w * inv * gb.w;
        float4 o;
        o.x = v0 * c0 - v1 * s0;  o.y = v0 * s0 + v1 * c0;
        o.z = v2 * c1 - v3 * s1;  o.w = v2 * s1 + v3 * c1;
        ((float4*)xr)[tid + 256] = o;
    }
}

// ============================================================================
// Flash attention (varlen key mask). One CTA = (batch, head, 64-query tile).
// 2-stage cp.async KV pipeline; O accumulated via wmma load-acc from smem.
// smem floats: Qs 8448 | Ks 2x8448 | Vs 2x8448 | Ss 4352 | Os 8448 | m/l
// ============================================================================
#define SM_QS 0
#define SM_KS 8448
#define SM_VS 25344
#define SM_SS 42240
#define SM_OS 46592
#define SM_M  55040
#define SM_L  55104
#define ATTN_SMEM_FLOATS 55168
#define ATTN_SMEM_BYTES  (ATTN_SMEM_FLOATS * 4)   /* 220672 */

__global__ __launch_bounds__(256) void attn_kernel(const int* __restrict__ seq_lens)
{
    extern __shared__ float sm[];
    float* Qs = sm + SM_QS;
    float* Ks = sm + SM_KS;
    float* Vs = sm + SM_VS;
    float* Ss = sm + SM_SS;
    float* Os = sm + SM_OS;
    float* mrow = sm + SM_M;
    float* lrow = sm + SM_L;

    const int b  = blockIdx.z;
    const int h  = blockIdx.y;
    const int q0 = blockIdx.x * 64;
    const int seqlen = seq_lens[b];
    const int tid  = threadIdx.x;
    const int warp = tid >> 5;
    const float scale = 0.08838834764831845f;   // 1/sqrt(128)

    const int ntiles = (seqlen + 63) >> 6;

    // KV tile issue: stage t&1, rows kv0..kv0+63 (always within SEQ buffer)
    auto issue_kv = [&](int t) {
        float* ks = Ks + (t & 1) * 8448;
        float* vs = Vs + (t & 1) * 8448;
        int r0 = tid >> 5, c0 = (tid & 31) * 4;
#pragma unroll
        for (int i = 0; i < 8; i++) {
            int r = r0 + 8 * i;
            size_t base = (size_t)(b * SEQ + t * 64 + r) * DIM + h * HDIM + c0;
            cp_async16(&ks[r * 132 + c0], g_k + base);
            cp_async16(&vs[r * 132 + c0], g_v + base);
        }
        CP_COMMIT();
    };

    issue_kv(0);

    // load Q tile, zero O, init m/l
#pragma unroll
    for (int i = 0; i < 8; i++) {
        int idx = tid + i * 256;
        int r = idx >> 5, c4 = idx & 31;
        const float* src = g_q + ((size_t)(b * SEQ + q0 + r) * DIM + h * HDIM + c4 * 4);
        *(float4*)&Qs[r * 132 + c4 * 4] = *(const float4*)src;
        *(float4*)&Os[r * 132 + c4 * 4] = make_float4(0.f, 0.f, 0.f, 0.f);
    }
    if (tid < 64) { mrow[tid] = -1e30f; lrow[tid] = 0.f; }
    __syncthreads();

    for (int t = 0; t < ntiles; t++) {
        CP_WAIT(0);                 // stage t&1 resident
        __syncthreads();
        if (t + 1 < ntiles) issue_kv(t + 1);

        const float* ks = Ks + (t & 1) * 8448;
        const float* vs = Vs + (t & 1) * 8448;
        const int kv0 = t * 64;

        // ---- S = scale * Q @ K^T  (64x64), warp grid 2x4 ----
        {
            const int wm = warp >> 2, wn = warp & 3;
            wmma::fragment<wmma::accumulator, 16, 16, 8, float> acc[2];
#pragma unroll
            for (int i = 0; i < 2; i++) wmma::fill_fragment(acc[i], 0.f);
#pragma unroll
            for (int kk = 0; kk < HDIM; kk += 8) {
                wmma::fragment<wmma::matrix_a, 16, 16, 8, wmma::precision::tf32, wmma::row_major> af[2];
                wmma::fragment<wmma::matrix_b, 16, 16, 8, wmma::precision::tf32, wmma::col_major> bf;
#pragma unroll
                for (int i = 0; i < 2; i++) {
                    wmma::load_matrix_sync(af[i], &Qs[(wm * 32 + i * 16) * 132 + kk], 132);
#pragma unroll
                    for (int t2 = 0; t2 < af[i].num_elements; t2++)
                        af[i].x[t2] = wmma::__float_to_tf32(af[i].x[t2]);
                }
                wmma::load_matrix_sync(bf, &ks[(wn * 16) * 132 + kk], 132);
#pragma unroll
                for (int t2 = 0; t2 < bf.num_elements; t2++)
                    bf.x[t2] = wmma::__float_to_tf32(bf.x[t2]);
#pragma unroll
                for (int i = 0; i < 2; i++)
                    wmma::mma_sync(acc[i], af[i], bf, acc[i]);
            }
#pragma unroll
            for (int i = 0; i < 2; i++) {
#pragma unroll
                for (int t2 = 0; t2 < acc[i].num_elements; t2++) acc[i].x[t2] *= scale;
                wmma::store_matrix_sync(&Ss[(wm * 32 + i * 16) * 68 + wn * 16],
                                        acc[i], 68, wmma::mem_row_major);
            }
        }
        __syncthreads();

        // ---- online softmax + rescale Os rows (4 threads per row) ----
        {
            const int r = tid >> 2, sub = tid & 3;
            const int c0 = sub * 16;
            const int nvalid = seqlen - kv0;    // >= 1
            float vmax = -1e30f;
#pragma unroll
            for (int c = c0; c < c0 + 16; c++) {
                float v = Ss[r * 68 + c];
                if (c < nvalid) vmax = fmaxf(vmax, v);
            }
            vmax = fmaxf(vmax, __shfl_xor_sync(0xffffffffu, vmax, 1));
            vmax = fmaxf(vmax, __shfl_xor_sync(0xffffffffu, vmax, 2));
            const float mold = mrow[r];
            const float mnew = fmaxf(mold, vmax);
            float sum = 0.f;
#pragma unroll
            for (int c = c0; c < c0 + 16; c++) {
                float p = (c < nvalid) ? __expf(Ss[r * 68 + c] - mnew) : 0.f;
                Ss[r * 68 + c] = p;
                sum += p;
            }
            sum += __shfl_xor_sync(0xffffffffu, sum, 1);
            sum += __shfl_xor_sync(0xffffffffu, sum, 2);
            const float rsc = __expf(mold - mnew);
            if (sub == 0) {
                lrow[r] = lrow[r] * rsc + sum;
                mrow[r] = mnew;
            }
            // rescale Os row r, this thread's 32 columns
            float4* orow = (float4*)&Os[r * 132];
#pragma unroll
            for (int j = 0; j < 8; j++) {
                float4 o = orow[sub * 8 + j];
                o.x *= rsc; o.y *= rsc; o.z *= rsc; o.w *= rsc;
                orow[sub * 8 + j] = o;
            }
        }
        __syncthreads();

        // ---- O += P @ V  (64x128), accumulate directly into Os ----
        {
            const int wm = warp >> 2, wn = warp & 3;
            wmma::fragment<wmma::accumulator, 16, 16, 8, float> acc[2][2];
#pragma unroll
            for (int i = 0; i < 2; i++)
#pragma unroll
                for (int j = 0; j < 2; j++)
                    wmma::load_matrix_sync(acc[i][j],
                        &Os[(wm * 32 + i * 16) * 132 + wn * 32 + j * 16],
                        132, wmma::mem_row_major);
#pragma unroll
            for (int kk = 0; kk < 64; kk += 8) {
                wmma::fragment<wmma::matrix_a, 16, 16, 8, wmma::precision::tf32, wmma::row_major> pf[2];
                wmma::fragment<wmma::matrix_b, 16, 16, 8, wmma::precision::tf32, wmma::row_major> vf[2];
#pragma unroll
                for (int i = 0; i < 2; i++) {
                    wmma::load_matrix_sync(pf[i], &Ss[(wm * 32 + i * 16) * 68 + kk], 68);
#pragma unroll
                    for (int t2 = 0; t2 < pf[i].num_elements; t2++)
                        pf[i].x[t2] = wmma::__float_to_tf32(pf[i].x[t2]);
                }
#pragma unroll
                for (int j = 0; j < 2; j++) {
                    wmma::load_matrix_sync(vf[j], &vs[kk * 132 + wn * 32 + j * 16], 132);
#pragma unroll
                    for (int t2 = 0; t2 < vf[j].num_elements; t2++)
                        vf[j].x[t2] = wmma::__float_to_tf32(vf[j].x[t2]);
                }
#pragma unroll
                for (int i = 0; i < 2; i++)
#pragma unroll
                    for (int j = 0; j < 2; j++)
                        wmma::mma_sync(acc[i][j], pf[i], vf[j], acc[i][j]);
            }
#pragma unroll
            for (int i = 0; i < 2; i++)
#pragma unroll
                for (int j = 0; j < 2; j++)
                    wmma::store_matrix_sync(&Os[(wm * 32 + i * 16) * 132 + wn * 32 + j * 16],
                                            acc[i][j], 132, wmma::mem_row_major);
        }
        __syncthreads();
    }

    // ---- write attn = O / l ----
#pragma unroll
    for (int i = 0; i < 8; i++) {
        int idx = tid + i * 256;
        int r = idx >> 5, c4 = idx & 31;
        float invl = 1.0f / lrow[r];
        float4 o = *(float4*)&Os[r * 132 + c4 * 4];
        o.x *= invl; o.y *= invl; o.z *= invl; o.w *= invl;
        float* dst = g_attn + ((size_t)(b * SEQ + q0 + r) * DIM + h * HDIM + c4 * 4);
        *(float4*)dst = o;
    }
}

// ============================================================================
// bias add (bo is zeros in this dataset, applied anyway for fidelity)
// ============================================================================
__global__ __launch_bounds__(256) void bias_add_kernel(float* __restrict__ out,
                                                       const float* __restrict__ bo)
{
    size_t i = (size_t)blockIdx.x * blockDim.x + threadIdx.x;
    float4 v = ((float4*)out)[i];
    float4 b = ((const float4*)bo)[i & 511];
    v.x += b.x; v.y += b.y; v.z += b.z; v.w += b.w;
    ((float4*)out)[i] = v;
}

// ============================================================================
extern "C" void kernel_launch(void* const* d_in, const int* in_sizes, int n_in,
                              void* d_out, int out_size)
{
    const float* x        = (const float*)d_in[0];
    const int*   seq_lens = (const int*)d_in[1];
    /* d_in[2] grid_sizes (int64) — unused by reference */
    const float* freqs    = (const float*)d_in[3];
    const float* Wq       = (const float*)d_in[4];
    const float* Wk       = (const float*)d_in[5];
    const float* Wv       = (const float*)d_in[6];
    const float* Wo       = (const float*)d_in[7];
    const float* bo       = (const float*)d_in[8];
    const float* gq       = (const float*)d_in[9];
    const float* gk       = (const float*)d_in[10];
    float* out = (float*)d_out;

    cudaFuncSetAttribute(gemm_nt_tf32, cudaFuncAttributeMaxDynamicSharedMemorySize,
                         GEMM_SMEM_BYTES);
    cudaFuncSetAttribute(attn_kernel, cudaFuncAttributeMaxDynamicSharedMemorySize,
                         ATTN_SMEM_BYTES);

    float *pq, *pk, *pv, *pa;
    cudaGetSymbolAddress((void**)&pq, g_q);
    cudaGetSymbolAddress((void**)&pk, g_k);
    cudaGetSymbolAddress((void**)&pv, g_v);
    cudaGetSymbolAddress((void**)&pa, g_attn);

    dim3 ggrid(DIM / 128, MROWS / 128);   // (16, 32)

    gemm_nt_tf32<<<ggrid, 256, GEMM_SMEM_BYTES>>>(x, Wq, pq, MROWS, DIM, DIM);
    gemm_nt_tf32<<<ggrid, 256, GEMM_SMEM_BYTES>>>(x, Wk, pk, MROWS, DIM, DIM);
    gemm_nt_tf32<<<ggrid, 256, GEMM_SMEM_BYTES>>>(x, Wv, pv, MROWS, DIM, DIM);

    rmsnorm_rope_kernel<<<dim3(MROWS, 2), 256>>>(pq, pk, gq, gk, freqs);

    attn_kernel<<<dim3(SEQ / 64, HEADS, BATCH), 256, ATTN_SMEM_BYTES>>>(seq_lens);

    gemm_nt_tf32<<<ggrid, 256, GEMM_SMEM_BYTES>>>(pa, Wo, out, MROWS, DIM, DIM);
    bias_add_kernel<<<(MROWS * DIM / 4) / 256, 256>>>(out, bo);
}

// round 11
// speedup vs baseline: 2.2450x; 1.9755x over previous
#include <cuda_runtime.h>
#include <mma.h>
#include <math.h>
#include <cstdint>

#define DIM    2048
#define SEQ    2048
#define BATCH  2
#define HEADS  16
#define HDIM   128
#define MROWS  (BATCH*SEQ)   /* 4096 */

// ---------------- scratch (device globals; no allocations) ----------------
__device__ float g_q[(size_t)MROWS * DIM];
__device__ float g_k[(size_t)MROWS * DIM];
__device__ float g_v[(size_t)MROWS * DIM];
__device__ float g_attn[(size_t)MROWS * DIM];
__device__ float g_xr[(size_t)MROWS * DIM];    // tf32-rounded A operand
__device__ float g_wr[(size_t)DIM * DIM];      // tf32-rounded B operand

// ---------------- cp.async helpers ----------------
__device__ __forceinline__ void cp_async16(void* dst, const void* src) {
    unsigned d = (unsigned)__cvta_generic_to_shared(dst);
    asm volatile("cp.async.cg.shared.global [%0], [%1], 16;\n" :: "r"(d), "l"(src));
}
#define CP_COMMIT() asm volatile("cp.async.commit_group;\n" ::: "memory")
#define CP_WAIT(n)  asm volatile("cp.async.wait_group %0;\n" :: "n"(n) : "memory")

// ---------------- raw tf32 mma (m16n8k8, row.col, fp32 accum) ----------------
// Operands are fp32 bit patterns already rounded to tf32-representable values,
// so the HW tf32 read is exact (identical math to wmma + __float_to_tf32).
__device__ __forceinline__ void mma_tf32(float d[4], const uint32_t a[4],
                                         const uint32_t b[2]) {
    asm volatile(
        "mma.sync.aligned.m16n8k8.row.col.f32.tf32.tf32.f32 "
        "{%0,%1,%2,%3}, {%4,%5,%6,%7}, {%8,%9}, {%0,%1,%2,%3};\n"
        : "+f"(d[0]), "+f"(d[1]), "+f"(d[2]), "+f"(d[3])
        : "r"(a[0]), "r"(a[1]), "r"(a[2]), "r"(a[3]), "r"(b[0]), "r"(b[1]));
}
__device__ __forceinline__ uint32_t f2u(float f) { return __float_as_uint(f); }
__device__ __forceinline__ float rtf32(float f) { return nvcuda::wmma::__float_to_tf32(f); }

// ============================================================================
// NT GEMM: C[M,2048] = A[M,2048] @ B[2048,2048]^T  (raw tf32 mma)
// 128x128 CTA tile, K-tile 32, 3-stage cp.async, 8 warps, warp tile 64x32.
// ============================================================================
#define GSTG 3
#define GSTAGE_F (128*36)
#define GEMM_SMEM_BYTES (2 * GSTG * GSTAGE_F * 4)   /* 110592 */

template <bool ROUND_OUT>
__global__ __launch_bounds__(256, 2) void gemm_mma_tf32(
    const float* __restrict__ A, const float* __restrict__ B, float* __restrict__ C)
{
    extern __shared__ float smg[];
    float* As = smg;
    float* Bs = smg + GSTG * GSTAGE_F;

    const int bm = blockIdx.y * 128;
    const int bn = blockIdx.x * 128;
    const int tid  = threadIdx.x;
    const int warp = tid >> 5;
    const int lane = tid & 31;
    const int g    = lane >> 2;        // 0..7
    const int tig  = lane & 3;         // 0..3
    const int wm = warp >> 2;          // 0..1  (64 rows)
    const int wn = warp & 3;           // 0..3  (32 cols)
    const int r0 = tid >> 3;           // load row 0..31
    const int c0 = (tid & 7) << 2;     // load col 0,4,..28

    const int ntiles = DIM / 32;       // 64

    float acc[4][4][4];
#pragma unroll
    for (int i = 0; i < 4; i++)
#pragma unroll
        for (int j = 0; j < 4; j++)
#pragma unroll
            for (int t = 0; t < 4; t++) acc[i][j][t] = 0.f;

    auto issue_tile = [&](int t) {
        int s = t % GSTG;
        int k0 = t * 32;
        float* as = As + s * GSTAGE_F;
        float* bs = Bs + s * GSTAGE_F;
#pragma unroll
        for (int i = 0; i < 4; i++) {
            int r = r0 + 32 * i;
            cp_async16(&as[r * 36 + c0], &A[(size_t)(bm + r) * DIM + k0 + c0]);
            cp_async16(&bs[r * 36 + c0], &B[(size_t)(bn + r) * DIM + k0 + c0]);
        }
    };

    issue_tile(0); CP_COMMIT();
    issue_tile(1); CP_COMMIT();

    for (int t = 0; t < ntiles; t++) {
        CP_WAIT(1);                 // tile t resident
        __syncthreads();            // also protects stage about to be overwritten
        if (t + 2 < ntiles) issue_tile(t + 2);
        CP_COMMIT();

        const float* as = As + (t % GSTG) * GSTAGE_F;
        const float* bs = Bs + (t % GSTG) * GSTAGE_F;

#pragma unroll
        for (int kk = 0; kk < 32; kk += 8) {
            uint32_t af[4][4];
#pragma unroll
            for (int i = 0; i < 4; i++) {
                const float* ap = &as[(wm * 64 + i * 16 + g) * 36 + kk + tig];
                af[i][0] = f2u(ap[0]);
                af[i][1] = f2u(ap[8 * 36]);
                af[i][2] = f2u(ap[4]);
                af[i][3] = f2u(ap[8 * 36 + 4]);
            }
            uint32_t bf[4][2];
#pragma unroll
            for (int j = 0; j < 4; j++) {
                const float* bp = &bs[(wn * 32 + j * 8 + g) * 36 + kk + tig];
                bf[j][0] = f2u(bp[0]);
                bf[j][1] = f2u(bp[4]);
            }
#pragma unroll
            for (int i = 0; i < 4; i++)
#pragma unroll
                for (int j = 0; j < 4; j++)
                    mma_tf32(acc[i][j], af[i], bf[j]);
        }
    }

    // epilogue: float2 stores (cols tig*2, tig*2+1 contiguous)
#pragma unroll
    for (int i = 0; i < 4; i++) {
        size_t ra = (size_t)(bm + wm * 64 + i * 16 + g);
        size_t rb = ra + 8;
#pragma unroll
        for (int j = 0; j < 4; j++) {
            size_t c = (size_t)(bn + wn * 32 + j * 8 + tig * 2);
            float2 v0, v1;
            if (ROUND_OUT) {
                v0 = make_float2(rtf32(acc[i][j][0]), rtf32(acc[i][j][1]));
                v1 = make_float2(rtf32(acc[i][j][2]), rtf32(acc[i][j][3]));
            } else {
                v0 = make_float2(acc[i][j][0], acc[i][j][1]);
                v1 = make_float2(acc[i][j][2], acc[i][j][3]);
            }
            *(float2*)&C[ra * DIM + c] = v0;
            *(float2*)&C[rb * DIM + c] = v1;
        }
    }
}

// ============================================================================
// elementwise round-to-tf32 (RN) so the HW tf32 operand read is exact
// ============================================================================
__global__ __launch_bounds__(256) void round_tf32_kernel(
    const float* __restrict__ in, float* __restrict__ out)
{
    size_t i = (size_t)blockIdx.x * blockDim.x + threadIdx.x;   // float4 index
    float4 v = ((const float4*)in)[i];
    v.x = rtf32(v.x); v.y = rtf32(v.y); v.z = rtf32(v.z); v.w = rtf32(v.w);
    ((float4*)out)[i] = v;
}

// ============================================================================
// Fused RMSNorm (full dim=2048) + interleaved RoPE, in-place on q or k.
// Output is rounded to tf32-representable fp32 (exact feed for attention mma).
// ============================================================================
__global__ __launch_bounds__(256) void rmsnorm_rope_kernel(
    float* __restrict__ q, float* __restrict__ k,
    const float* __restrict__ gq, const float* __restrict__ gk,
    const float* __restrict__ freqs)
{
    float* x = (blockIdx.y == 0) ? q : k;
    const float* g = (blockIdx.y == 0) ? gq : gk;
    const int row = blockIdx.x;
    const int s   = row & (SEQ - 1);
    float* xr = x + (size_t)row * DIM;
    const int tid = threadIdx.x;

    float4 a = ((const float4*)xr)[tid];
    float4 b = ((const float4*)xr)[tid + 256];

    float ss = a.x*a.x + a.y*a.y + a.z*a.z + a.w*a.w
             + b.x*b.x + b.y*b.y + b.z*b.z + b.w*b.w;
#pragma unroll
    for (int o = 16; o > 0; o >>= 1)
        ss += __shfl_xor_sync(0xffffffffu, ss, o);

    __shared__ float red[8];
    if ((tid & 31) == 0) red[tid >> 5] = ss;
    __syncthreads();
    float tot = 0.f;
#pragma unroll
    for (int w = 0; w < 8; w++) tot += red[w];

    const float inv = rsqrtf(tot * (1.0f / (float)DIM) + 1e-6f);

    float4 ga = ((const float4*)g)[tid];
    float4 gb = ((const float4*)g)[tid + 256];
    const float* fr = freqs + (size_t)s * (HDIM / 2);

    {
        int p0 = 2 * tid, p1 = 2 * tid + 1;
        float s0, c0, s1, c1;
        sincosf(fr[p0 & 63], &s0, &c0);
        sincosf(fr[p1 & 63], &s1, &c1);
        float v0 = a.x * inv * ga.x, v1 = a.y * inv * ga.y;
        float v2 = a.z * inv * ga.z, v3 = a.w * inv * ga.w;
        float4 o;
        o.x = rtf32(v0 * c0 - v1 * s0);  o.y = rtf32(v0 * s0 + v1 * c0);
        o.z = rtf32(v2 * c1 - v3 * s1);  o.w = rtf32(v2 * s1 + v3 * c1);
        ((float4*)xr)[tid] = o;
    }
    {
        int p0 = 512 + 2 * tid, p1 = 513 + 2 * tid;
        float s0, c0, s1, c1;
        sincosf(fr[p0 & 63], &s0, &c0);
        sincosf(fr[p1 & 63], &s1, &c1);
        float v0 = b.x * inv * gb.x, v1 = b.y * inv * gb.y;
        float v2 = b.z * inv * gb.z, v3 = b.w * inv * gb.w;
        float4 o;
        o.x = rtf32(v0 * c0 - v1 * s0);  o.y = rtf32(v0 * s0 + v1 * c0);
        o.z = rtf32(v2 * c1 - v3 * s1);  o.w = rtf32(v2 * s1 + v3 * c1);
        ((float4*)xr)[tid + 256] = o;
    }
}

// ============================================================================
// Flash attention (varlen key mask), raw tf32 mma.
// One CTA = (batch, head, 64-query tile); 2-stage cp.async KV pipeline.
// smem floats: Qs 8448 | Ks 2x8448 | Vs 2x8448 | Ss 4352 | Os 8448 | m/l
// ============================================================================
#define SM_QS 0
#define SM_KS 8448
#define SM_VS 25344
#define SM_SS 42240
#define SM_OS 46592
#define SM_M  55040
#define SM_L  55104
#define ATTN_SMEM_FLOATS 55168
#define ATTN_SMEM_BYTES  (ATTN_SMEM_FLOATS * 4)   /* 220672 */

__global__ __launch_bounds__(256) void attn_kernel(const int* __restrict__ seq_lens)
{
    extern __shared__ float sm[];
    float* Qs = sm + SM_QS;
    float* Ks = sm + SM_KS;
    float* Vs = sm + SM_VS;
    float* Ss = sm + SM_SS;
    float* Os = sm + SM_OS;
    float* mrow = sm + SM_M;
    float* lrow = sm + SM_L;

    const int b  = blockIdx.z;
    const int h  = blockIdx.y;
    const int q0 = blockIdx.x * 64;
    const int seqlen = seq_lens[b];
    const int tid  = threadIdx.x;
    const int warp = tid >> 5;
    const int lane = tid & 31;
    const int g    = lane >> 2;
    const int tig  = lane & 3;
    const float scale = 0.08838834764831845f;   // 1/sqrt(128)

    const int ntiles = (seqlen + 63) >> 6;

    auto issue_kv = [&](int t) {
        float* ks = Ks + (t & 1) * 8448;
        float* vs = Vs + (t & 1) * 8448;
        int r0 = tid >> 5, c0 = (tid & 31) * 4;
#pragma unroll
        for (int i = 0; i < 8; i++) {
            int r = r0 + 8 * i;
            size_t base = (size_t)(b * SEQ + t * 64 + r) * DIM + h * HDIM + c0;
            cp_async16(&ks[r * 132 + c0], g_k + base);
            cp_async16(&vs[r * 132 + c0], g_v + base);
        }
        CP_COMMIT();
    };

    issue_kv(0);

#pragma unroll
    for (int i = 0; i < 8; i++) {
        int idx = tid + i * 256;
        int r = idx >> 5, c4 = idx & 31;
        const float* src = g_q + ((size_t)(b * SEQ + q0 + r) * DIM + h * HDIM + c4 * 4);
        *(float4*)&Qs[r * 132 + c4 * 4] = *(const float4*)src;
        *(float4*)&Os[r * 132 + c4 * 4] = make_float4(0.f, 0.f, 0.f, 0.f);
    }
    if (tid < 64) { mrow[tid] = -1e30f; lrow[tid] = 0.f; }
    __syncthreads();

    for (int t = 0; t < ntiles; t++) {
        CP_WAIT(0);
        __syncthreads();
        if (t + 1 < ntiles) issue_kv(t + 1);

        const float* ks = Ks + (t & 1) * 8448;
        const float* vs = Vs + (t & 1) * 8448;
        const int kv0 = t * 64;

        // ---- S = scale * Q @ K^T (64x64); warp tile 32x16 (2x2 mma tiles) ----
        {
            const int wm = warp >> 2, wn = warp & 3;
            float sa[2][2][4];
#pragma unroll
            for (int i = 0; i < 2; i++)
#pragma unroll
                for (int j = 0; j < 2; j++)
#pragma unroll
                    for (int u = 0; u < 4; u++) sa[i][j][u] = 0.f;

#pragma unroll
            for (int kk = 0; kk < HDIM; kk += 8) {
                uint32_t af[2][4];
#pragma unroll
                for (int i = 0; i < 2; i++) {
                    const float* ap = &Qs[(wm * 32 + i * 16 + g) * 132 + kk + tig];
                    af[i][0] = f2u(ap[0]);
                    af[i][1] = f2u(ap[8 * 132]);
                    af[i][2] = f2u(ap[4]);
                    af[i][3] = f2u(ap[8 * 132 + 4]);
                }
                uint32_t bf[2][2];
#pragma unroll
                for (int j = 0; j < 2; j++) {
                    const float* bp = &ks[(wn * 16 + j * 8 + g) * 132 + kk + tig];
                    bf[j][0] = f2u(bp[0]);
                    bf[j][1] = f2u(bp[4]);
                }
#pragma unroll
                for (int i = 0; i < 2; i++)
#pragma unroll
                    for (int j = 0; j < 2; j++)
                        mma_tf32(sa[i][j], af[i], bf[j]);
            }
#pragma unroll
            for (int i = 0; i < 2; i++) {
                int r = wm * 32 + i * 16 + g;
#pragma unroll
                for (int j = 0; j < 2; j++) {
                    int c = wn * 16 + j * 8 + tig * 2;
                    *(float2*)&Ss[r * 68 + c] =
                        make_float2(sa[i][j][0] * scale, sa[i][j][1] * scale);
                    *(float2*)&Ss[(r + 8) * 68 + c] =
                        make_float2(sa[i][j][2] * scale, sa[i][j][3] * scale);
                }
            }
        }
        __syncthreads();

        // ---- online softmax + rescale Os rows (4 threads per row) ----
        {
            const int r = tid >> 2, sub = tid & 3;
            const int c0s = sub * 16;
            const int nvalid = seqlen - kv0;
            float vmax = -1e30f;
#pragma unroll
            for (int c = c0s; c < c0s + 16; c++) {
                float v = Ss[r * 68 + c];
                if (c < nvalid) vmax = fmaxf(vmax, v);
            }
            vmax = fmaxf(vmax, __shfl_xor_sync(0xffffffffu, vmax, 1));
            vmax = fmaxf(vmax, __shfl_xor_sync(0xffffffffu, vmax, 2));
            const float mold = mrow[r];
            const float mnew = fmaxf(mold, vmax);
            float sum = 0.f;
#pragma unroll
            for (int c = c0s; c < c0s + 16; c++) {
                float p = (c < nvalid) ? __expf(Ss[r * 68 + c] - mnew) : 0.f;
                Ss[r * 68 + c] = rtf32(p);     // rounded for exact tf32 mma read
                sum += p;
            }
            sum += __shfl_xor_sync(0xffffffffu, sum, 1);
            sum += __shfl_xor_sync(0xffffffffu, sum, 2);
            const float rsc = __expf(mold - mnew);
            if (sub == 0) {
                lrow[r] = lrow[r] * rsc + sum;
                mrow[r] = mnew;
            }
            float4* orow = (float4*)&Os[r * 132];
#pragma unroll
            for (int j = 0; j < 8; j++) {
                float4 o = orow[sub * 8 + j];
                o.x *= rsc; o.y *= rsc; o.z *= rsc; o.w *= rsc;
                orow[sub * 8 + j] = o;
            }
        }
        __syncthreads();

        // ---- O += P @ V (64x128); warp tile 32x32 (2x4 mma tiles) ----
        {
            const int wm = warp >> 2, wn = warp & 3;
            float oa[2][4][4];
#pragma unroll
            for (int i = 0; i < 2; i++) {
                int r = wm * 32 + i * 16 + g;
#pragma unroll
                for (int j = 0; j < 4; j++) {
                    int c = wn * 32 + j * 8 + tig * 2;
                    float2 v0 = *(float2*)&Os[r * 132 + c];
                    float2 v1 = *(float2*)&Os[(r + 8) * 132 + c];
                    oa[i][j][0] = v0.x; oa[i][j][1] = v0.y;
                    oa[i][j][2] = v1.x; oa[i][j][3] = v1.y;
                }
            }
#pragma unroll
            for (int kk = 0; kk < 64; kk += 8) {
                uint32_t af[2][4];
#pragma unroll
                for (int i = 0; i < 2; i++) {
                    const float* ap = &Ss[(wm * 32 + i * 16 + g) * 68 + kk + tig];
                    af[i][0] = f2u(ap[0]);
                    af[i][1] = f2u(ap[8 * 68]);
                    af[i][2] = f2u(ap[4]);
                    af[i][3] = f2u(ap[8 * 68 + 4]);
                }
                uint32_t bf[4][2];
#pragma unroll
                for (int j = 0; j < 4; j++) {
                    // col-frag: row=k, col=n ; Vs[k][n] row-major
                    const float* bp = &vs[(kk + tig) * 132 + wn * 32 + j * 8 + g];
                    bf[j][0] = f2u(bp[0]);
                    bf[j][1] = f2u(bp[4 * 132]);
                }
#pragma unroll
                for (int i = 0; i < 2; i++)
#pragma unroll
                    for (int j = 0; j < 4; j++)
                        mma_tf32(oa[i][j], af[i], bf[j]);
            }
#pragma unroll
            for (int i = 0; i < 2; i++) {
                int r = wm * 32 + i * 16 + g;
#pragma unroll
                for (int j = 0; j < 4; j++) {
                    int c = wn * 32 + j * 8 + tig * 2;
                    *(float2*)&Os[r * 132 + c] = make_float2(oa[i][j][0], oa[i][j][1]);
                    *(float2*)&Os[(r + 8) * 132 + c] = make_float2(oa[i][j][2], oa[i][j][3]);
                }
            }
        }
        __syncthreads();
    }

    // ---- write attn = O / l, rounded to tf32 (feeds the O-proj GEMM) ----
#pragma unroll
    for (int i = 0; i < 8; i++) {
        int idx = tid + i * 256;
        int r = idx >> 5, c4 = idx & 31;
        float invl = 1.0f / lrow[r];
        float4 o = *(float4*)&Os[r * 132 + c4 * 4];
        o.x = rtf32(o.x * invl); o.y = rtf32(o.y * invl);
        o.z = rtf32(o.z * invl); o.w = rtf32(o.w * invl);
        float* dst = g_attn + ((size_t)(b * SEQ + q0 + r) * DIM + h * HDIM + c4 * 4);
        *(float4*)dst = o;
    }
}

// ============================================================================
// bias add
// ============================================================================
__global__ __launch_bounds__(256) void bias_add_kernel(float* __restrict__ out,
                                                       const float* __restrict__ bo)
{
    size_t i = (size_t)blockIdx.x * blockDim.x + threadIdx.x;
    float4 v = ((float4*)out)[i];
    float4 b = ((const float4*)bo)[i & 511];
    v.x += b.x; v.y += b.y; v.z += b.z; v.w += b.w;
    ((float4*)out)[i] = v;
}

// ============================================================================
extern "C" void kernel_launch(void* const* d_in, const int* in_sizes, int n_in,
                              void* d_out, int out_size)
{
    const float* x        = (const float*)d_in[0];
    const int*   seq_lens = (const int*)d_in[1];
    /* d_in[2] grid_sizes (int64) — unused by reference */
    const float* freqs    = (const float*)d_in[3];
    const float* Wq       = (const float*)d_in[4];
    const float* Wk       = (const float*)d_in[5];
    const float* Wv       = (const float*)d_in[6];
    const float* Wo       = (const float*)d_in[7];
    const float* bo       = (const float*)d_in[8];
    const float* gq       = (const float*)d_in[9];
    const float* gk       = (const float*)d_in[10];
    float* out = (float*)d_out;

    cudaFuncSetAttribute(gemm_mma_tf32<false>,
                         cudaFuncAttributeMaxDynamicSharedMemorySize, GEMM_SMEM_BYTES);
    cudaFuncSetAttribute(gemm_mma_tf32<true>,
                         cudaFuncAttributeMaxDynamicSharedMemorySize, GEMM_SMEM_BYTES);
    cudaFuncSetAttribute(attn_kernel,
                         cudaFuncAttributeMaxDynamicSharedMemorySize, ATTN_SMEM_BYTES);

    float *pq, *pk, *pv, *pa, *pxr, *pwr;
    cudaGetSymbolAddress((void**)&pq,  g_q);
    cudaGetSymbolAddress((void**)&pk,  g_k);
    cudaGetSymbolAddress((void**)&pv,  g_v);
    cudaGetSymbolAddress((void**)&pa,  g_attn);
    cudaGetSymbolAddress((void**)&pxr, g_xr);
    cudaGetSymbolAddress((void**)&pwr, g_wr);

    const dim3 ggrid(DIM / 128, MROWS / 128);     // (16, 32)
    const int RND_X = (MROWS * DIM / 4) / 256;    // 8192 blocks
    const int RND_W = (DIM * DIM / 4) / 256;      // 4096 blocks

    // pre-round operands to tf32-representable fp32 (RN), then raw-mma GEMMs
    round_tf32_kernel<<<RND_X, 256>>>(x, pxr);

    round_tf32_kernel<<<RND_W, 256>>>(Wq, pwr);
    gemm_mma_tf32<false><<<ggrid, 256, GEMM_SMEM_BYTES>>>(pxr, pwr, pq);

    round_tf32_kernel<<<RND_W, 256>>>(Wk, pwr);
    gemm_mma_tf32<false><<<ggrid, 256, GEMM_SMEM_BYTES>>>(pxr, pwr, pk);

    round_tf32_kernel<<<RND_W, 256>>>(Wv, pwr);
    gemm_mma_tf32<true><<<ggrid, 256, GEMM_SMEM_BYTES>>>(pxr, pwr, pv);  // V rounded

    rmsnorm_rope_kernel<<<dim3(MROWS, 2), 256>>>(pq, pk, gq, gk, freqs); // rounds q,k

    attn_kernel<<<dim3(SEQ / 64, HEADS, BATCH), 256, ATTN_SMEM_BYTES>>>(seq_lens);
    // attention output is already tf32-rounded

    round_tf32_kernel<<<RND_W, 256>>>(Wo, pwr);
    gemm_mma_tf32<false><<<ggrid, 256, GEMM_SMEM_BYTES>>>(pa, pwr, out);

    bias_add_kernel<<<(MROWS * DIM / 4) / 256, 256>>>(out, bo);
}

// round 12
// speedup vs baseline: 2.7943x; 1.2447x over previous
#include <cuda_runtime.h>
#include <mma.h>
#include <math.h>
#include <cstdint>

#define DIM    2048
#define SEQ    2048
#define BATCH  2
#define HEADS  16
#define HDIM   128
#define MROWS  (BATCH*SEQ)   /* 4096 */

// ---------------- scratch (device globals; no allocations) ----------------
__device__ float g_q[(size_t)MROWS * DIM];
__device__ float g_k[(size_t)MROWS * DIM];
__device__ float g_v[(size_t)MROWS * DIM];
__device__ float g_attn[(size_t)MROWS * DIM];
__device__ float g_xr[(size_t)MROWS * DIM];    // tf32-rounded A operand
__device__ float g_wr[(size_t)DIM * DIM];      // tf32-rounded B operand

// ---------------- cp.async helpers ----------------
__device__ __forceinline__ void cp_async16(void* dst, const void* src) {
    unsigned d = (unsigned)__cvta_generic_to_shared(dst);
    asm volatile("cp.async.cg.shared.global [%0], [%1], 16;\n" :: "r"(d), "l"(src));
}
#define CP_COMMIT() asm volatile("cp.async.commit_group;\n" ::: "memory")
#define CP_WAIT(n)  asm volatile("cp.async.wait_group %0;\n" :: "n"(n) : "memory")

// ---------------- raw tf32 mma (m16n8k8, row.col, fp32 accum) ----------------
// Operands are fp32 bit patterns already rounded to tf32-representable values,
// so the HW tf32 operand read is exact.
__device__ __forceinline__ void mma_tf32(float d[4], const uint32_t a[4],
                                         const uint32_t b[2]) {
    asm volatile(
        "mma.sync.aligned.m16n8k8.row.col.f32.tf32.tf32.f32 "
        "{%0,%1,%2,%3}, {%4,%5,%6,%7}, {%8,%9}, {%0,%1,%2,%3};\n"
        : "+f"(d[0]), "+f"(d[1]), "+f"(d[2]), "+f"(d[3])
        : "r"(a[0]), "r"(a[1]), "r"(a[2]), "r"(a[3]), "r"(b[0]), "r"(b[1]));
}
__device__ __forceinline__ uint32_t f2u(float f) { return __float_as_uint(f); }
__device__ __forceinline__ float rtf32(float f) { return nvcuda::wmma::__float_to_tf32(f); }

// ============================================================================
// NT GEMM: C[M,2048] = A[M,2048] @ B[2048,2048]^T  (raw tf32 mma)
// 128x128 CTA tile, K-tile 32, 3-stage cp.async, 4 warps, warp tile 64x64.
// Per warp per k=8: 32 LDS.32 + 32 HMMA (1.0 ratio vs 1.5 before).
// ============================================================================
#define GSTG 3
#define GSTAGE_F (128*36)
#define GEMM_SMEM_BYTES (2 * GSTG * GSTAGE_F * 4)   /* 110592 */

template <bool ROUND_OUT>
__global__ __launch_bounds__(128, 2) void gemm_mma_tf32(
    const float* __restrict__ A, const float* __restrict__ B, float* __restrict__ C)
{
    extern __shared__ float smg[];
    float* As = smg;
    float* Bs = smg + GSTG * GSTAGE_F;

    const int bm = blockIdx.y * 128;
    const int bn = blockIdx.x * 128;
    const int tid  = threadIdx.x;
    const int warp = tid >> 5;
    const int lane = tid & 31;
    const int g    = lane >> 2;        // 0..7
    const int tig  = lane & 3;         // 0..3
    const int wm = warp >> 1;          // 0..1  (64 rows)
    const int wn = warp & 1;           // 0..1  (64 cols)

    const int ntiles = DIM / 32;       // 64

    float acc[4][8][4];
#pragma unroll
    for (int i = 0; i < 4; i++)
#pragma unroll
        for (int j = 0; j < 8; j++)
#pragma unroll
            for (int t = 0; t < 4; t++) acc[i][j][t] = 0.f;

    auto issue_tile = [&](int t) {
        int s = t % GSTG;
        int k0 = t * 32;
        float* as = As + s * GSTAGE_F;
        float* bs = Bs + s * GSTAGE_F;
#pragma unroll
        for (int i = 0; i < 8; i++) {
            int idx = tid + i * 128;           // 0..1023 float4 slots
            int r = idx >> 3;
            int c = (idx & 7) << 2;
            cp_async16(&as[r * 36 + c], &A[(size_t)(bm + r) * DIM + k0 + c]);
            cp_async16(&bs[r * 36 + c], &B[(size_t)(bn + r) * DIM + k0 + c]);
        }
    };

    issue_tile(0); CP_COMMIT();
    issue_tile(1); CP_COMMIT();

    for (int t = 0; t < ntiles; t++) {
        CP_WAIT(1);                 // tile t resident
        __syncthreads();            // also protects stage about to be overwritten
        if (t + 2 < ntiles) issue_tile(t + 2);
        CP_COMMIT();

        const float* as = As + (t % GSTG) * GSTAGE_F;
        const float* bs = Bs + (t % GSTG) * GSTAGE_F;

#pragma unroll
        for (int kk = 0; kk < 32; kk += 8) {
            uint32_t af[4][4];
#pragma unroll
            for (int i = 0; i < 4; i++) {
                const float* ap = &as[(wm * 64 + i * 16 + g) * 36 + kk + tig];
                af[i][0] = f2u(ap[0]);
                af[i][1] = f2u(ap[8 * 36]);
                af[i][2] = f2u(ap[4]);
                af[i][3] = f2u(ap[8 * 36 + 4]);
            }
            uint32_t bf[8][2];
#pragma unroll
            for (int j = 0; j < 8; j++) {
                const float* bp = &bs[(wn * 64 + j * 8 + g) * 36 + kk + tig];
                bf[j][0] = f2u(bp[0]);
                bf[j][1] = f2u(bp[4]);
            }
#pragma unroll
            for (int i = 0; i < 4; i++)
#pragma unroll
                for (int j = 0; j < 8; j++)
                    mma_tf32(acc[i][j], af[i], bf[j]);
        }
    }

    // epilogue: float2 stores (cols tig*2, tig*2+1 contiguous)
#pragma unroll
    for (int i = 0; i < 4; i++) {
        size_t ra = (size_t)(bm + wm * 64 + i * 16 + g);
        size_t rb = ra + 8;
#pragma unroll
        for (int j = 0; j < 8; j++) {
            size_t c = (size_t)(bn + wn * 64 + j * 8 + tig * 2);
            float2 v0, v1;
            if (ROUND_OUT) {
                v0 = make_float2(rtf32(acc[i][j][0]), rtf32(acc[i][j][1]));
                v1 = make_float2(rtf32(acc[i][j][2]), rtf32(acc[i][j][3]));
            } else {
                v0 = make_float2(acc[i][j][0], acc[i][j][1]);
                v1 = make_float2(acc[i][j][2], acc[i][j][3]);
            }
            *(float2*)&C[ra * DIM + c] = v0;
            *(float2*)&C[rb * DIM + c] = v1;
        }
    }
}

// ============================================================================
// elementwise round-to-tf32 (RN) so the HW tf32 operand read is exact
// ============================================================================
__global__ __launch_bounds__(256) void round_tf32_kernel(
    const float* __restrict__ in, float* __restrict__ out)
{
    size_t i = (size_t)blockIdx.x * blockDim.x + threadIdx.x;   // float4 index
    float4 v = ((const float4*)in)[i];
    v.x = rtf32(v.x); v.y = rtf32(v.y); v.z = rtf32(v.z); v.w = rtf32(v.w);
    ((float4*)out)[i] = v;
}

// ============================================================================
// Fused RMSNorm (full dim=2048) + interleaved RoPE, in-place on q or k.
// Output rounded to tf32-representable fp32 (exact feed for attention mma).
// ============================================================================
__global__ __launch_bounds__(256) void rmsnorm_rope_kernel(
    float* __restrict__ q, float* __restrict__ k,
    const float* __restrict__ gq, const float* __restrict__ gk,
    const float* __restrict__ freqs)
{
    float* x = (blockIdx.y == 0) ? q : k;
    const float* g = (blockIdx.y == 0) ? gq : gk;
    const int row = blockIdx.x;
    const int s   = row & (SEQ - 1);
    float* xr = x + (size_t)row * DIM;
    const int tid = threadIdx.x;

    float4 a = ((const float4*)xr)[tid];
    float4 b = ((const float4*)xr)[tid + 256];

    float ss = a.x*a.x + a.y*a.y + a.z*a.z + a.w*a.w
             + b.x*b.x + b.y*b.y + b.z*b.z + b.w*b.w;
#pragma unroll
    for (int o = 16; o > 0; o >>= 1)
        ss += __shfl_xor_sync(0xffffffffu, ss, o);

    __shared__ float red[8];
    if ((tid & 31) == 0) red[tid >> 5] = ss;
    __syncthreads();
    float tot = 0.f;
#pragma unroll
    for (int w = 0; w < 8; w++) tot += red[w];

    const float inv = rsqrtf(tot * (1.0f / (float)DIM) + 1e-6f);

    float4 ga = ((const float4*)g)[tid];
    float4 gb = ((const float4*)g)[tid + 256];
    const float* fr = freqs + (size_t)s * (HDIM / 2);

    {
        int p0 = 2 * tid, p1 = 2 * tid + 1;
        float s0, c0, s1, c1;
        sincosf(fr[p0 & 63], &s0, &c0);
        sincosf(fr[p1 & 63], &s1, &c1);
        float v0 = a.x * inv * ga.x, v1 = a.y * inv * ga.y;
        float v2 = a.z * inv * ga.z, v3 = a.w * inv * ga.w;
        float4 o;
        o.x = rtf32(v0 * c0 - v1 * s0);  o.y = rtf32(v0 * s0 + v1 * c0);
        o.z = rtf32(v2 * c1 - v3 * s1);  o.w = rtf32(v2 * s1 + v3 * c1);
        ((float4*)xr)[tid] = o;
    }
    {
        int p0 = 512 + 2 * tid, p1 = 513 + 2 * tid;
        float s0, c0, s1, c1;
        sincosf(fr[p0 & 63], &s0, &c0);
        sincosf(fr[p1 & 63], &s1, &c1);
        float v0 = b.x * inv * gb.x, v1 = b.y * inv * gb.y;
        float v2 = b.z * inv * gb.z, v3 = b.w * inv * gb.w;
        float4 o;
        o.x = rtf32(v0 * c0 - v1 * s0);  o.y = rtf32(v0 * s0 + v1 * c0);
        o.z = rtf32(v2 * c1 - v3 * s1);  o.w = rtf32(v2 * s1 + v3 * c1);
        ((float4*)xr)[tid + 256] = o;
    }
}

// ============================================================================
// Flash attention (varlen key mask), raw tf32 mma, O in registers.
// One CTA = (batch, head, 64-query tile); 2-stage cp.async KV pipeline.
// Per kv tile: QK mma -> fused online softmax (2 smem reductions) -> PV mma.
// smem floats: Qs 8448 | Ks 2x8448 | Vs 2x8448 | Ss 4352 | m/l | rmax/rsum
// ============================================================================
#define SM_QS   0
#define SM_KS   8448
#define SM_VS   25344
#define SM_SS   42240
#define SM_M    46592
#define SM_L    46656
#define SM_RMAX 46720   /* [64][4] */
#define SM_RSUM 46976   /* [64][4] */
#define ATTN_SMEM_FLOATS 47232
#define ATTN_SMEM_BYTES  (ATTN_SMEM_FLOATS * 4)   /* 188928 */

__global__ __launch_bounds__(256) void attn_kernel(const int* __restrict__ seq_lens)
{
    extern __shared__ float sm[];
    float* Qs   = sm + SM_QS;
    float* Ks   = sm + SM_KS;
    float* Vs   = sm + SM_VS;
    float* Ss   = sm + SM_SS;
    float* mrow = sm + SM_M;
    float* lrow = sm + SM_L;
    float* rmax = sm + SM_RMAX;
    float* rsum = sm + SM_RSUM;

    const int b  = blockIdx.z;
    const int h  = blockIdx.y;
    const int q0 = blockIdx.x * 64;
    const int seqlen = seq_lens[b];
    const int tid  = threadIdx.x;
    const int warp = tid >> 5;
    const int lane = tid & 31;
    const int g    = lane >> 2;
    const int tig  = lane & 3;
    const int wm = warp >> 2;          // 0..1 (query half)
    const int wn = warp & 3;           // 0..3 (key / hdim quarter)
    const float scale = 0.08838834764831845f;   // 1/sqrt(128)

    const int ntiles = (seqlen + 63) >> 6;

    auto issue_kv = [&](int t) {
        float* ks = Ks + (t & 1) * 8448;
        float* vs = Vs + (t & 1) * 8448;
        int r0 = tid >> 5, c0 = (tid & 31) * 4;
#pragma unroll
        for (int i = 0; i < 8; i++) {
            int r = r0 + 8 * i;
            size_t base = (size_t)(b * SEQ + t * 64 + r) * DIM + h * HDIM + c0;
            cp_async16(&ks[r * 132 + c0], g_k + base);
            cp_async16(&vs[r * 132 + c0], g_v + base);
        }
        CP_COMMIT();
    };

    issue_kv(0);

    // load Q tile; init m/l
#pragma unroll
    for (int i = 0; i < 8; i++) {
        int idx = tid + i * 256;
        int r = idx >> 5, c4 = idx & 31;
        const float* src = g_q + ((size_t)(b * SEQ + q0 + r) * DIM + h * HDIM + c4 * 4);
        *(float4*)&Qs[r * 132 + c4 * 4] = *(const float4*)src;
    }
    if (tid < 64) { mrow[tid] = -1e30f; lrow[tid] = 0.f; }

    // O accumulator in registers: warp tile 32x32 (i=2 m-tiles, j=4 n-tiles)
    float oa[2][4][4];
#pragma unroll
    for (int i = 0; i < 2; i++)
#pragma unroll
        for (int j = 0; j < 4; j++)
#pragma unroll
            for (int u = 0; u < 4; u++) oa[i][j][u] = 0.f;

    __syncthreads();

    for (int t = 0; t < ntiles; t++) {
        CP_WAIT(0);
        __syncthreads();                       // sync #1 (KV resident / stage safe)
        if (t + 1 < ntiles) issue_kv(t + 1);

        const float* ks = Ks + (t & 1) * 8448;
        const float* vs = Vs + (t & 1) * 8448;
        const int kv0 = t * 64;
        const int nvalid = seqlen - kv0;       // >= 1

        // ---- S = scale * Q @ K^T (64x64); warp tile 32x16 (2x2 mma tiles) ----
        float sa[2][2][4];
#pragma unroll
        for (int i = 0; i < 2; i++)
#pragma unroll
            for (int j = 0; j < 2; j++)
#pragma unroll
                for (int u = 0; u < 4; u++) sa[i][j][u] = 0.f;

#pragma unroll
        for (int kk = 0; kk < HDIM; kk += 8) {
            uint32_t af[2][4];
#pragma unroll
            for (int i = 0; i < 2; i++) {
                const float* ap = &Qs[(wm * 32 + i * 16 + g) * 132 + kk + tig];
                af[i][0] = f2u(ap[0]);
                af[i][1] = f2u(ap[8 * 132]);
                af[i][2] = f2u(ap[4]);
                af[i][3] = f2u(ap[8 * 132 + 4]);
            }
            uint32_t bf[2][2];
#pragma unroll
            for (int j = 0; j < 2; j++) {
                const float* bp = &ks[(wn * 16 + j * 8 + g) * 132 + kk + tig];
                bf[j][0] = f2u(bp[0]);
                bf[j][1] = f2u(bp[4]);
            }
#pragma unroll
            for (int i = 0; i < 2; i++)
#pragma unroll
                for (int j = 0; j < 2; j++)
                    mma_tf32(sa[i][j], af[i], bf[j]);
        }

        // scale + masked per-thread row maxes; reduce over tig; write rmax
        // thread covers rows r(i,hh) = wm*32 + i*16 + g + hh*8, cols wn*16+j*8+tig*2(+1)
        float pmax[2][2];
#pragma unroll
        for (int i = 0; i < 2; i++)
#pragma unroll
            for (int hh = 0; hh < 2; hh++) pmax[i][hh] = -1e30f;
#pragma unroll
        for (int i = 0; i < 2; i++)
#pragma unroll
            for (int j = 0; j < 2; j++) {
                int cl = wn * 16 + j * 8 + tig * 2;
                bool v0 = cl < nvalid, v1 = (cl + 1) < nvalid;
#pragma unroll
                for (int u = 0; u < 4; u++) sa[i][j][u] *= scale;
                if (v0) { pmax[i][0] = fmaxf(pmax[i][0], sa[i][j][0]);
                          pmax[i][1] = fmaxf(pmax[i][1], sa[i][j][2]); }
                if (v1) { pmax[i][0] = fmaxf(pmax[i][0], sa[i][j][1]);
                          pmax[i][1] = fmaxf(pmax[i][1], sa[i][j][3]); }
            }
#pragma unroll
        for (int i = 0; i < 2; i++)
#pragma unroll
            for (int hh = 0; hh < 2; hh++) {
                float v = pmax[i][hh];
                v = fmaxf(v, __shfl_xor_sync(0xffffffffu, v, 1));
                v = fmaxf(v, __shfl_xor_sync(0xffffffffu, v, 2));
                pmax[i][hh] = v;
            }
        if (tig == 0) {
#pragma unroll
            for (int i = 0; i < 2; i++)
#pragma unroll
                for (int hh = 0; hh < 2; hh++)
                    rmax[(wm * 32 + i * 16 + g + hh * 8) * 4 + wn] = pmax[i][hh];
        }
        __syncthreads();                       // sync #2 (rmax ready)

        // per-row: mnew/rsc; exp + store P; rescale oa; partial sums
        float mnewr[2][2], rscr[2][2], psum[2][2];
#pragma unroll
        for (int i = 0; i < 2; i++)
#pragma unroll
            for (int hh = 0; hh < 2; hh++) {
                int r = wm * 32 + i * 16 + g + hh * 8;
                float vmax = fmaxf(fmaxf(rmax[r * 4 + 0], rmax[r * 4 + 1]),
                                   fmaxf(rmax[r * 4 + 2], rmax[r * 4 + 3]));
                float mold = mrow[r];
                float mnew = fmaxf(mold, vmax);
                mnewr[i][hh] = mnew;
                rscr[i][hh]  = __expf(mold - mnew);
                psum[i][hh]  = 0.f;
            }
#pragma unroll
        for (int i = 0; i < 2; i++)
#pragma unroll
            for (int j = 0; j < 2; j++) {
                int cl = wn * 16 + j * 8 + tig * 2;
                bool v0 = cl < nvalid, v1 = (cl + 1) < nvalid;
                float p00 = v0 ? __expf(sa[i][j][0] - mnewr[i][0]) : 0.f;
                float p01 = v1 ? __expf(sa[i][j][1] - mnewr[i][0]) : 0.f;
                float p10 = v0 ? __expf(sa[i][j][2] - mnewr[i][1]) : 0.f;
                float p11 = v1 ? __expf(sa[i][j][3] - mnewr[i][1]) : 0.f;
                psum[i][0] += p00 + p01;
                psum[i][1] += p10 + p11;
                int r0 = wm * 32 + i * 16 + g;
                *(float2*)&Ss[r0 * 68 + cl]       = make_float2(rtf32(p00), rtf32(p01));
                *(float2*)&Ss[(r0 + 8) * 68 + cl] = make_float2(rtf32(p10), rtf32(p11));
            }
#pragma unroll
        for (int i = 0; i < 2; i++)
#pragma unroll
            for (int hh = 0; hh < 2; hh++) {
                float v = psum[i][hh];
                v += __shfl_xor_sync(0xffffffffu, v, 1);
                v += __shfl_xor_sync(0xffffffffu, v, 2);
                psum[i][hh] = v;
            }
        if (tig == 0) {
#pragma unroll
            for (int i = 0; i < 2; i++)
#pragma unroll
                for (int hh = 0; hh < 2; hh++)
                    rsum[(wm * 32 + i * 16 + g + hh * 8) * 4 + wn] = psum[i][hh];
        }
        // rescale O accumulators by rsc (per row)
#pragma unroll
        for (int i = 0; i < 2; i++)
#pragma unroll
            for (int j = 0; j < 4; j++) {
                oa[i][j][0] *= rscr[i][0]; oa[i][j][1] *= rscr[i][0];
                oa[i][j][2] *= rscr[i][1]; oa[i][j][3] *= rscr[i][1];
            }
        __syncthreads();                       // sync #3 (Ss + rsum ready)

        // one writer per row updates m/l (read next tile after sync #1)
        if (wn == 0 && tig == 0) {
#pragma unroll
            for (int i = 0; i < 2; i++)
#pragma unroll
                for (int hh = 0; hh < 2; hh++) {
                    int r = wm * 32 + i * 16 + g + hh * 8;
                    float tot = rsum[r * 4 + 0] + rsum[r * 4 + 1]
                              + rsum[r * 4 + 2] + rsum[r * 4 + 3];
                    lrow[r] = lrow[r] * rscr[i][hh] + tot;
                    mrow[r] = mnewr[i][hh];
                }
        }

        // ---- O += P @ V (64x128); warp tile 32x32 (2x4 mma tiles) ----
#pragma unroll
        for (int kk = 0; kk < 64; kk += 8) {
            uint32_t af[2][4];
#pragma unroll
            for (int i = 0; i < 2; i++) {
                const float* ap = &Ss[(wm * 32 + i * 16 + g) * 68 + kk + tig];
                af[i][0] = f2u(ap[0]);
                af[i][1] = f2u(ap[8 * 68]);
                af[i][2] = f2u(ap[4]);
                af[i][3] = f2u(ap[8 * 68 + 4]);
            }
            uint32_t bf[4][2];
#pragma unroll
            for (int j = 0; j < 4; j++) {
                const float* bp = &vs[(kk + tig) * 132 + wn * 32 + j * 8 + g];
                bf[j][0] = f2u(bp[0]);
                bf[j][1] = f2u(bp[4 * 132]);
            }
#pragma unroll
            for (int i = 0; i < 2; i++)
#pragma unroll
                for (int j = 0; j < 4; j++)
                    mma_tf32(oa[i][j], af[i], bf[j]);
        }
    }

    __syncthreads();                           // lrow final

    // ---- write attn = O / l, rounded to tf32 (feeds the O-proj GEMM) ----
#pragma unroll
    for (int i = 0; i < 2; i++) {
        int r0 = wm * 32 + i * 16 + g;
        float invl0 = 1.0f / lrow[r0];
        float invl1 = 1.0f / lrow[r0 + 8];
        size_t row0 = (size_t)(b * SEQ + q0 + r0) * DIM + h * HDIM;
        size_t row1 = row0 + (size_t)8 * DIM;
#pragma unroll
        for (int j = 0; j < 4; j++) {
            int c = wn * 32 + j * 8 + tig * 2;
            *(float2*)&g_attn[row0 + c] =
                make_float2(rtf32(oa[i][j][0] * invl0), rtf32(oa[i][j][1] * invl0));
            *(float2*)&g_attn[row1 + c] =
                make_float2(rtf32(oa[i][j][2] * invl1), rtf32(oa[i][j][3] * invl1));
        }
    }
}

// ============================================================================
// bias add
// ============================================================================
__global__ __launch_bounds__(256) void bias_add_kernel(float* __restrict__ out,
                                                       const float* __restrict__ bo)
{
    size_t i = (size_t)blockIdx.x * blockDim.x + threadIdx.x;
    float4 v = ((float4*)out)[i];
    float4 b = ((const float4*)bo)[i & 511];
    v.x += b.x; v.y += b.y; v.z += b.z; v.w += b.w;
    ((float4*)out)[i] = v;
}

// ============================================================================
extern "C" void kernel_launch(void* const* d_in, const int* in_sizes, int n_in,
                              void* d_out, int out_size)
{
    const float* x        = (const float*)d_in[0];
    const int*   seq_lens = (const int*)d_in[1];
    /* d_in[2] grid_sizes (int64) — unused by reference */
    const float* freqs    = (const float*)d_in[3];
    const float* Wq       = (const float*)d_in[4];
    const float* Wk       = (const float*)d_in[5];
    const float* Wv       = (const float*)d_in[6];
    const float* Wo       = (const float*)d_in[7];
    const float* bo       = (const float*)d_in[8];
    const float* gq       = (const float*)d_in[9];
    const float* gk       = (const float*)d_in[10];
    float* out = (float*)d_out;

    cudaFuncSetAttribute(gemm_mma_tf32<false>,
                         cudaFuncAttributeMaxDynamicSharedMemorySize, GEMM_SMEM_BYTES);
    cudaFuncSetAttribute(gemm_mma_tf32<true>,
                         cudaFuncAttributeMaxDynamicSharedMemorySize, GEMM_SMEM_BYTES);
    cudaFuncSetAttribute(attn_kernel,
                         cudaFuncAttributeMaxDynamicSharedMemorySize, ATTN_SMEM_BYTES);

    float *pq, *pk, *pv, *pa, *pxr, *pwr;
    cudaGetSymbolAddress((void**)&pq,  g_q);
    cudaGetSymbolAddress((void**)&pk,  g_k);
    cudaGetSymbolAddress((void**)&pv,  g_v);
    cudaGetSymbolAddress((void**)&pa,  g_attn);
    cudaGetSymbolAddress((void**)&pxr, g_xr);
    cudaGetSymbolAddress((void**)&pwr, g_wr);

    const dim3 ggrid(DIM / 128, MROWS / 128);     // (16, 32)
    const int RND_X = (MROWS * DIM / 4) / 256;    // 8192 blocks
    const int RND_W = (DIM * DIM / 4) / 256;      // 4096 blocks

    // pre-round operands to tf32-representable fp32 (RN), then raw-mma GEMMs
    round_tf32_kernel<<<RND_X, 256>>>(x, pxr);

    round_tf32_kernel<<<RND_W, 256>>>(Wq, pwr);
    gemm_mma_tf32<false><<<ggrid, 128, GEMM_SMEM_BYTES>>>(pxr, pwr, pq);

    round_tf32_kernel<<<RND_W, 256>>>(Wk, pwr);
    gemm_mma_tf32<false><<<ggrid, 128, GEMM_SMEM_BYTES>>>(pxr, pwr, pk);

    round_tf32_kernel<<<RND_W, 256>>>(Wv, pwr);
    gemm_mma_tf32<true><<<ggrid, 128, GEMM_SMEM_BYTES>>>(pxr, pwr, pv);  // V rounded

    rmsnorm_rope_kernel<<<dim3(MROWS, 2), 256>>>(pq, pk, gq, gk, freqs); // rounds q,k

    attn_kernel<<<dim3(SEQ / 64, HEADS, BATCH), 256, ATTN_SMEM_BYTES>>>(seq_lens);
    // attention output is already tf32-rounded

    round_tf32_kernel<<<RND_W, 256>>>(Wo, pwr);
    gemm_mma_tf32<false><<<ggrid, 128, GEMM_SMEM_BYTES>>>(pa, pwr, out);

    bias_add_kernel<<<(MROWS * DIM / 4) / 256, 256>>>(out, bo);
}

// round 13
// speedup vs baseline: 3.1730x; 1.1355x over previous
#include <cuda_runtime.h>
#include <mma.h>
#include <math.h>
#include <cstdint>

#define DIM    2048
#define SEQ    2048
#define BATCH  2
#define HEADS  16
#define HDIM   128
#define MROWS  (BATCH*SEQ)   /* 4096 */

// ---------------- scratch (device globals; no allocations) ----------------
__device__ float g_q[(size_t)MROWS * DIM];
__device__ float g_k[(size_t)MROWS * DIM];
__device__ float g_v[(size_t)MROWS * DIM];
__device__ float g_attn[(size_t)MROWS * DIM];
__device__ float g_xr[(size_t)MROWS * DIM];      // tf32-rounded activations
__device__ float g_wr4[(size_t)4 * DIM * DIM];   // tf32-rounded Wq|Wk|Wv|Wo

// ---------------- cp.async helpers ----------------
__device__ __forceinline__ void cp_async16(void* dst, const void* src) {
    unsigned d = (unsigned)__cvta_generic_to_shared(dst);
    asm volatile("cp.async.cg.shared.global [%0], [%1], 16;\n" :: "r"(d), "l"(src));
}
#define CP_COMMIT() asm volatile("cp.async.commit_group;\n" ::: "memory")
#define CP_WAIT(n)  asm volatile("cp.async.wait_group %0;\n" :: "n"(n) : "memory")

// ---------------- raw tf32 mma (m16n8k8, row.col, fp32 accum) ----------------
// Operands are fp32 bit patterns already rounded to tf32-representable values,
// so the HW tf32 operand read is exact.
__device__ __forceinline__ void mma_tf32(float d[4], const uint32_t a[4],
                                         const uint32_t b[2]) {
    asm volatile(
        "mma.sync.aligned.m16n8k8.row.col.f32.tf32.tf32.f32 "
        "{%0,%1,%2,%3}, {%4,%5,%6,%7}, {%8,%9}, {%0,%1,%2,%3};\n"
        : "+f"(d[0]), "+f"(d[1]), "+f"(d[2]), "+f"(d[3])
        : "r"(a[0]), "r"(a[1]), "r"(a[2]), "r"(a[3]), "r"(b[0]), "r"(b[1]));
}
__device__ __forceinline__ uint32_t f2u(float f) { return __float_as_uint(f); }
__device__ __forceinline__ float rtf32(float f) { return nvcuda::wmma::__float_to_tf32(f); }

// ============================================================================
// NT GEMM: C[M,2048] = A[M,2048] @ B[2048,2048]^T  (raw tf32 mma)
// 128x128 CTA tile, K-tile 32, 3-stage cp.async, 4 warps, warp tile 64x64.
// ============================================================================
#define GSTG 3
#define GSTAGE_F (128*36)
#define GEMM_SMEM_BYTES (2 * GSTG * GSTAGE_F * 4)   /* 110592 */

template <bool ROUND_OUT, bool ADD_BIAS>
__global__ __launch_bounds__(128, 2) void gemm_mma_tf32(
    const float* __restrict__ A, const float* __restrict__ B,
    float* __restrict__ C, const float* __restrict__ bias)
{
    extern __shared__ float smg[];
    float* As = smg;
    float* Bs = smg + GSTG * GSTAGE_F;

    const int bm = blockIdx.y * 128;
    const int bn = blockIdx.x * 128;
    const int tid  = threadIdx.x;
    const int warp = tid >> 5;
    const int lane = tid & 31;
    const int g    = lane >> 2;        // 0..7
    const int tig  = lane & 3;         // 0..3
    const int wm = warp >> 1;          // 0..1  (64 rows)
    const int wn = warp & 1;           // 0..1  (64 cols)

    const int ntiles = DIM / 32;       // 64

    float acc[4][8][4];
#pragma unroll
    for (int i = 0; i < 4; i++)
#pragma unroll
        for (int j = 0; j < 8; j++)
#pragma unroll
            for (int t = 0; t < 4; t++) acc[i][j][t] = 0.f;

    auto issue_tile = [&](int t) {
        int s = t % GSTG;
        int k0 = t * 32;
        float* as = As + s * GSTAGE_F;
        float* bs = Bs + s * GSTAGE_F;
#pragma unroll
        for (int i = 0; i < 8; i++) {
            int idx = tid + i * 128;           // 0..1023 float4 slots
            int r = idx >> 3;
            int c = (idx & 7) << 2;
            cp_async16(&as[r * 36 + c], &A[(size_t)(bm + r) * DIM + k0 + c]);
            cp_async16(&bs[r * 36 + c], &B[(size_t)(bn + r) * DIM + k0 + c]);
        }
    };

    issue_tile(0); CP_COMMIT();
    issue_tile(1); CP_COMMIT();

    for (int t = 0; t < ntiles; t++) {
        CP_WAIT(1);                 // tile t resident
        __syncthreads();            // also protects stage about to be overwritten
        if (t + 2 < ntiles) issue_tile(t + 2);
        CP_COMMIT();

        const float* as = As + (t % GSTG) * GSTAGE_F;
        const float* bs = Bs + (t % GSTG) * GSTAGE_F;

#pragma unroll
        for (int kk = 0; kk < 32; kk += 8) {
            uint32_t af[4][4];
#pragma unroll
            for (int i = 0; i < 4; i++) {
                const float* ap = &as[(wm * 64 + i * 16 + g) * 36 + kk + tig];
                af[i][0] = f2u(ap[0]);
                af[i][1] = f2u(ap[8 * 36]);
                af[i][2] = f2u(ap[4]);
                af[i][3] = f2u(ap[8 * 36 + 4]);
            }
            uint32_t bf[8][2];
#pragma unroll
            for (int j = 0; j < 8; j++) {
                const float* bp = &bs[(wn * 64 + j * 8 + g) * 36 + kk + tig];
                bf[j][0] = f2u(bp[0]);
                bf[j][1] = f2u(bp[4]);
            }
#pragma unroll
            for (int i = 0; i < 4; i++)
#pragma unroll
                for (int j = 0; j < 8; j++)
                    mma_tf32(acc[i][j], af[i], bf[j]);
        }
    }

    // epilogue: float2 stores (cols tig*2, tig*2+1 contiguous)
#pragma unroll
    for (int i = 0; i < 4; i++) {
        size_t ra = (size_t)(bm + wm * 64 + i * 16 + g);
        size_t rb = ra + 8;
#pragma unroll
        for (int j = 0; j < 8; j++) {
            size_t c = (size_t)(bn + wn * 64 + j * 8 + tig * 2);
            float b0 = 0.f, b1 = 0.f;
            if (ADD_BIAS) { b0 = bias[c]; b1 = bias[c + 1]; }
            float2 v0, v1;
            if (ROUND_OUT) {
                v0 = make_float2(rtf32(acc[i][j][0]), rtf32(acc[i][j][1]));
                v1 = make_float2(rtf32(acc[i][j][2]), rtf32(acc[i][j][3]));
            } else {
                v0 = make_float2(acc[i][j][0] + b0, acc[i][j][1] + b1);
                v1 = make_float2(acc[i][j][2] + b0, acc[i][j][3] + b1);
            }
            *(float2*)&C[ra * DIM + c] = v0;
            *(float2*)&C[rb * DIM + c] = v1;
        }
    }
}

// ============================================================================
// elementwise round-to-tf32 (RN)
// ============================================================================
__global__ __launch_bounds__(256) void round_tf32_kernel(
    const float* __restrict__ in, float* __restrict__ out)
{
    size_t i = (size_t)blockIdx.x * blockDim.x + threadIdx.x;   // float4 index
    float4 v = ((const float4*)in)[i];
    v.x = rtf32(v.x); v.y = rtf32(v.y); v.z = rtf32(v.z); v.w = rtf32(v.w);
    ((float4*)out)[i] = v;
}

// round all 4 weight matrices into g_wr4 in one launch
__global__ __launch_bounds__(256) void round4_w_kernel(
    const float* __restrict__ w0, const float* __restrict__ w1,
    const float* __restrict__ w2, const float* __restrict__ w3,
    float* __restrict__ out)
{
    const size_t PER = (size_t)DIM * DIM / 4;       // float4 per matrix
    size_t i = (size_t)blockIdx.x * blockDim.x + threadIdx.x;
    int w = (int)(i / PER);
    size_t r = i - (size_t)w * PER;
    const float* src = (w == 0) ? w0 : (w == 1) ? w1 : (w == 2) ? w2 : w3;
    float4 v = ((const float4*)src)[r];
    v.x = rtf32(v.x); v.y = rtf32(v.y); v.z = rtf32(v.z); v.w = rtf32(v.w);
    ((float4*)out)[i] = v;
}

// ============================================================================
// Fused RMSNorm (full dim=2048) + interleaved RoPE, in-place on q or k.
// Output rounded to tf32-representable fp32 (exact feed for attention mma).
// ============================================================================
__global__ __launch_bounds__(256) void rmsnorm_rope_kernel(
    float* __restrict__ q, float* __restrict__ k,
    const float* __restrict__ gq, const float* __restrict__ gk,
    const float* __restrict__ freqs)
{
    float* x = (blockIdx.y == 0) ? q : k;
    const float* g = (blockIdx.y == 0) ? gq : gk;
    const int row = blockIdx.x;
    const int s   = row & (SEQ - 1);
    float* xr = x + (size_t)row * DIM;
    const int tid = threadIdx.x;

    float4 a = ((const float4*)xr)[tid];
    float4 b = ((const float4*)xr)[tid + 256];

    float ss = a.x*a.x + a.y*a.y + a.z*a.z + a.w*a.w
             + b.x*b.x + b.y*b.y + b.z*b.z + b.w*b.w;
#pragma unroll
    for (int o = 16; o > 0; o >>= 1)
        ss += __shfl_xor_sync(0xffffffffu, ss, o);

    __shared__ float red[8];
    if ((tid & 31) == 0) red[tid >> 5] = ss;
    __syncthreads();
    float tot = 0.f;
#pragma unroll
    for (int w = 0; w < 8; w++) tot += red[w];

    const float inv = rsqrtf(tot * (1.0f / (float)DIM) + 1e-6f);

    float4 ga = ((const float4*)g)[tid];
    float4 gb = ((const float4*)g)[tid + 256];
    const float* fr = freqs + (size_t)s * (HDIM / 2);

    {
        int p0 = 2 * tid, p1 = 2 * tid + 1;
        float s0, c0, s1, c1;
        sincosf(fr[p0 & 63], &s0, &c0);
        sincosf(fr[p1 & 63], &s1, &c1);
        float v0 = a.x * inv * ga.x, v1 = a.y * inv * ga.y;
        float v2 = a.z * inv * ga.z, v3 = a.w * inv * ga.w;
        float4 o;
        o.x = rtf32(v0 * c0 - v1 * s0);  o.y = rtf32(v0 * s0 + v1 * c0);
        o.z = rtf32(v2 * c1 - v3 * s1);  o.w = rtf32(v2 * s1 + v3 * c1);
        ((float4*)xr)[tid] = o;
    }
    {
        int p0 = 512 + 2 * tid, p1 = 513 + 2 * tid;
        float s0, c0, s1, c1;
        sincosf(fr[p0 & 63], &s0, &c0);
        sincosf(fr[p1 & 63], &s1, &c1);
        float v0 = b.x * inv * gb.x, v1 = b.y * inv * gb.y;
        float v2 = b.z * inv * gb.z, v3 = b.w * inv * gb.w;
        float4 o;
        o.x = rtf32(v0 * c0 - v1 * s0);  o.y = rtf32(v0 * s0 + v1 * c0);
        o.z = rtf32(v2 * c1 - v3 * s1);  o.w = rtf32(v2 * s1 + v3 * c1);
        ((float4*)xr)[tid + 256] = o;
    }
}

// ============================================================================
// Flash attention (varlen key mask), raw tf32 mma, O in registers.
// One CTA = (batch, head, 128-query tile), 256 threads (8 warps).
// K double-buffered (cp.async), V single-buffered (its own group, waited
// after softmax — latency hidden under QK+softmax).
// QK: S=128x64, warps 4x2, warp tile 32x32 (LDS/mma = 2.0).
// PV: O=128x128, warps 4x2, warp tile 32x64 (LDS/mma = 1.5).
// smem floats: Qs 128x132 | Ks 2x64x132 | Vs 64x136 | Ss 128x68 | m/l/rmax/rsum
// ============================================================================
#define BLKQ    128
#define SM_QS   0
#define SM_KS   16896
#define SM_VS   33792
#define SM_SS   42496
#define SM_M    51200   /* [128] */
#define SM_L    51328   /* [128] */
#define SM_RMAX 51456   /* [128][2] */
#define SM_RSUM 51712   /* [128][2] */
#define ATTN_SMEM_FLOATS 51968
#define ATTN_SMEM_BYTES  (ATTN_SMEM_FLOATS * 4)   /* 207872 */

__global__ __launch_bounds__(256) void attn_kernel(const int* __restrict__ seq_lens)
{
    extern __shared__ float sm[];
    float* Qs   = sm + SM_QS;
    float* Ks   = sm + SM_KS;
    float* Vs   = sm + SM_VS;
    float* Ss   = sm + SM_SS;
    float* mrow = sm + SM_M;
    float* lrow = sm + SM_L;
    float* rmax = sm + SM_RMAX;
    float* rsum = sm + SM_RSUM;

    const int b  = blockIdx.z;
    const int h  = blockIdx.y;
    const int q0 = blockIdx.x * BLKQ;
    const int seqlen = seq_lens[b];
    const int tid  = threadIdx.x;
    const int warp = tid >> 5;
    const int lane = tid & 31;
    const int g    = lane >> 2;
    const int tig  = lane & 3;
    const int wm = warp >> 1;          // 0..3 (32-query rows)
    const int wn = warp & 1;           // 0..1
    const float scale = 0.08838834764831845f;   // 1/sqrt(128)

    const int ntiles = (seqlen + 63) >> 6;

    auto issue_k = [&](int t) {        // no commit
        float* ks = Ks + (t & 1) * 8448;
        int r0 = tid >> 5, c0 = (tid & 31) * 4;
#pragma unroll
        for (int i = 0; i < 8; i++) {
            int r = r0 + 8 * i;
            size_t base = (size_t)(b * SEQ + t * 64 + r) * DIM + h * HDIM + c0;
            cp_async16(&ks[r * 132 + c0], g_k + base);
        }
    };
    auto issue_v = [&](int t) {        // no commit
        int r0 = tid >> 5, c0 = (tid & 31) * 4;
#pragma unroll
        for (int i = 0; i < 8; i++) {
            int r = r0 + 8 * i;
            size_t base = (size_t)(b * SEQ + t * 64 + r) * DIM + h * HDIM + c0;
            cp_async16(&Vs[r * 136 + c0], g_v + base);
        }
    };

    issue_k(0); CP_COMMIT();

    // load Q tile (128 rows); init m/l
#pragma unroll
    for (int i = 0; i < 16; i++) {
        int idx = tid + i * 256;               // 0..4095 float4 slots
        int r = idx >> 5, c4 = idx & 31;
        const float* src = g_q + ((size_t)(b * SEQ + q0 + r) * DIM + h * HDIM + c4 * 4);
        *(float4*)&Qs[r * 132 + c4 * 4] = *(const float4*)src;
    }
    if (tid < BLKQ) { mrow[tid] = -1e30f; lrow[tid] = 0.f; }

    // O accumulator: warp tile 32x64 (i=2 m-tiles, j=8 n-tiles)
    float oa[2][8][4];
#pragma unroll
    for (int i = 0; i < 2; i++)
#pragma unroll
        for (int j = 0; j < 8; j++)
#pragma unroll
            for (int u = 0; u < 4; u++) oa[i][j][u] = 0.f;

    for (int t = 0; t < ntiles; t++) {
        CP_WAIT(0);
        __syncthreads();                       // sync1: K(t), Q, V consumed
        issue_v(t); CP_COMMIT();               // group: V(t)
        if (t + 1 < ntiles) issue_k(t + 1);
        CP_COMMIT();                           // group: K(t+1) (possibly empty)

        const float* ks = Ks + (t & 1) * 8448;
        const int kv0 = t * 64;
        const int nvalid = seqlen - kv0;       // >= 1

        // ---- S = scale * Q @ K^T (128x64); warp tile 32x32 (2x4 tiles) ----
        float sa[2][4][4];
#pragma unroll
        for (int i = 0; i < 2; i++)
#pragma unroll
            for (int j = 0; j < 4; j++)
#pragma unroll
                for (int u = 0; u < 4; u++) sa[i][j][u] = 0.f;

#pragma unroll
        for (int kk = 0; kk < HDIM; kk += 8) {
            uint32_t af[2][4];
#pragma unroll
            for (int i = 0; i < 2; i++) {
                const float* ap = &Qs[(wm * 32 + i * 16 + g) * 132 + kk + tig];
                af[i][0] = f2u(ap[0]);
                af[i][1] = f2u(ap[8 * 132]);
                af[i][2] = f2u(ap[4]);
                af[i][3] = f2u(ap[8 * 132 + 4]);
            }
            uint32_t bf[4][2];
#pragma unroll
            for (int j = 0; j < 4; j++) {
                const float* bp = &ks[(wn * 32 + j * 8 + g) * 132 + kk + tig];
                bf[j][0] = f2u(bp[0]);
                bf[j][1] = f2u(bp[4]);
            }
#pragma unroll
            for (int i = 0; i < 2; i++)
#pragma unroll
                for (int j = 0; j < 4; j++)
                    mma_tf32(sa[i][j], af[i], bf[j]);
        }

        // scale + masked per-thread row maxes; reduce over tig; write rmax
        float pmax[2][2];
#pragma unroll
        for (int i = 0; i < 2; i++)
#pragma unroll
            for (int hh = 0; hh < 2; hh++) pmax[i][hh] = -1e30f;
#pragma unroll
        for (int i = 0; i < 2; i++)
#pragma unroll
            for (int j = 0; j < 4; j++) {
                int cl = wn * 32 + j * 8 + tig * 2;
                bool v0 = cl < nvalid, v1 = (cl + 1) < nvalid;
#pragma unroll
                for (int u = 0; u < 4; u++) sa[i][j][u] *= scale;
                if (v0) { pmax[i][0] = fmaxf(pmax[i][0], sa[i][j][0]);
                          pmax[i][1] = fmaxf(pmax[i][1], sa[i][j][2]); }
                if (v1) { pmax[i][0] = fmaxf(pmax[i][0], sa[i][j][1]);
                          pmax[i][1] = fmaxf(pmax[i][1], sa[i][j][3]); }
            }
#pragma unroll
        for (int i = 0; i < 2; i++)
#pragma unroll
            for (int hh = 0; hh < 2; hh++) {
                float v = pmax[i][hh];
                v = fmaxf(v, __shfl_xor_sync(0xffffffffu, v, 1));
                v = fmaxf(v, __shfl_xor_sync(0xffffffffu, v, 2));
                pmax[i][hh] = v;
            }
        if (tig == 0) {
#pragma unroll
            for (int i = 0; i < 2; i++)
#pragma unroll
                for (int hh = 0; hh < 2; hh++)
                    rmax[(wm * 32 + i * 16 + g + hh * 8) * 2 + wn] = pmax[i][hh];
        }
        __syncthreads();                       // sync2: rmax ready

        // per-row mnew/rsc; exp + store P; rescale oa; partial sums
        float mnewr[2][2], rscr[2][2], psum[2][2];
#pragma unroll
        for (int i = 0; i < 2; i++)
#pragma unroll
            for (int hh = 0; hh < 2; hh++) {
                int r = wm * 32 + i * 16 + g + hh * 8;
                float vmax = fmaxf(rmax[r * 2 + 0], rmax[r * 2 + 1]);
                float mold = mrow[r];
                float mnew = fmaxf(mold, vmax);
                mnewr[i][hh] = mnew;
                rscr[i][hh]  = __expf(mold - mnew);
                psum[i][hh]  = 0.f;
            }
#pragma unroll
        for (int i = 0; i < 2; i++)
#pragma unroll
            for (int j = 0; j < 4; j++) {
                int cl = wn * 32 + j * 8 + tig * 2;
                bool v0 = cl < nvalid, v1 = (cl + 1) < nvalid;
                float p00 = v0 ? __expf(sa[i][j][0] - mnewr[i][0]) : 0.f;
                float p01 = v1 ? __expf(sa[i][j][1] - mnewr[i][0]) : 0.f;
                float p10 = v0 ? __expf(sa[i][j][2] - mnewr[i][1]) : 0.f;
                float p11 = v1 ? __expf(sa[i][j][3] - mnewr[i][1]) : 0.f;
                psum[i][0] += p00 + p01;
                psum[i][1] += p10 + p11;
                int r0 = wm * 32 + i * 16 + g;
                *(float2*)&Ss[r0 * 68 + cl]       = make_float2(rtf32(p00), rtf32(p01));
                *(float2*)&Ss[(r0 + 8) * 68 + cl] = make_float2(rtf32(p10), rtf32(p11));
            }
#pragma unroll
        for (int i = 0; i < 2; i++)
#pragma unroll
            for (int hh = 0; hh < 2; hh++) {
                float v = psum[i][hh];
                v += __shfl_xor_sync(0xffffffffu, v, 1);
                v += __shfl_xor_sync(0xffffffffu, v, 2);
                psum[i][hh] = v;
            }
        if (tig == 0) {
#pragma unroll
            for (int i = 0; i < 2; i++)
#pragma unroll
                for (int hh = 0; hh < 2; hh++)
                    rsum[(wm * 32 + i * 16 + g + hh * 8) * 2 + wn] = psum[i][hh];
        }
        // rescale O accumulators (rows match sa rows)
#pragma unroll
        for (int i = 0; i < 2; i++)
#pragma unroll
            for (int j = 0; j < 8; j++) {
                oa[i][j][0] *= rscr[i][0]; oa[i][j][1] *= rscr[i][0];
                oa[i][j][2] *= rscr[i][1]; oa[i][j][3] *= rscr[i][1];
            }
        CP_WAIT(1);                            // V(t) resident (K(t+1) in flight)
        __syncthreads();                       // sync3: Ss, rsum, Vs visible

        // one writer per row updates m/l (next read after sync1 of t+1)
        if (wn == 0 && tig == 0) {
#pragma unroll
            for (int i = 0; i < 2; i++)
#pragma unroll
                for (int hh = 0; hh < 2; hh++) {
                    int r = wm * 32 + i * 16 + g + hh * 8;
                    float tot = rsum[r * 2 + 0] + rsum[r * 2 + 1];
                    lrow[r] = lrow[r] * rscr[i][hh] + tot;
                    mrow[r] = mnewr[i][hh];
                }
        }

        // ---- O += P @ V (128x128); warp tile 32x64 (2x8 tiles) ----
#pragma unroll
        for (int kk = 0; kk < 64; kk += 8) {
            uint32_t af[2][4];
#pragma unroll
            for (int i = 0; i < 2; i++) {
                const float* ap = &Ss[(wm * 32 + i * 16 + g) * 68 + kk + tig];
                af[i][0] = f2u(ap[0]);
                af[i][1] = f2u(ap[8 * 68]);
                af[i][2] = f2u(ap[4]);
                af[i][3] = f2u(ap[8 * 68 + 4]);
            }
            uint32_t bf[8][2];
#pragma unroll
            for (int j = 0; j < 8; j++) {
                const float* bp = &Vs[(kk + tig) * 136 + wn * 64 + j * 8 + g];
                bf[j][0] = f2u(bp[0]);
                bf[j][1] = f2u(bp[4 * 136]);
            }
#pragma unroll
            for (int i = 0; i < 2; i++)
#pragma unroll
                for (int j = 0; j < 8; j++)
                    mma_tf32(oa[i][j], af[i], bf[j]);
        }
    }

    __syncthreads();                           // lrow final

    // ---- write attn = O / l, rounded to tf32 (feeds the O-proj GEMM) ----
#pragma unroll
    for (int i = 0; i < 2; i++) {
        int r0 = wm * 32 + i * 16 + g;
        float invl0 = 1.0f / lrow[r0];
        float invl1 = 1.0f / lrow[r0 + 8];
        size_t row0 = (size_t)(b * SEQ + q0 + r0) * DIM + h * HDIM;
        size_t row1 = row0 + (size_t)8 * DIM;
#pragma unroll
        for (int j = 0; j < 8; j++) {
            int c = wn * 64 + j * 8 + tig * 2;
            *(float2*)&g_attn[row0 + c] =
                make_float2(rtf32(oa[i][j][0] * invl0), rtf32(oa[i][j][1] * invl0));
            *(float2*)&g_attn[row1 + c] =
                make_float2(rtf32(oa[i][j][2] * invl1), rtf32(oa[i][j][3] * invl1));
        }
    }
}

// ============================================================================
extern "C" void kernel_launch(void* const* d_in, const int* in_sizes, int n_in,
                              void* d_out, int out_size)
{
    const float* x        = (const float*)d_in[0];
    const int*   seq_lens = (const int*)d_in[1];
    /* d_in[2] grid_sizes (int64) — unused by reference */
    const float* freqs    = (const float*)d_in[3];
    const float* Wq       = (const float*)d_in[4];
    const float* Wk       = (const float*)d_in[5];
    const float* Wv       = (const float*)d_in[6];
    const float* Wo       = (const float*)d_in[7];
    const float* bo       = (const float*)d_in[8];
    const float* gq       = (const float*)d_in[9];
    const float* gk       = (const float*)d_in[10];
    float* out = (float*)d_out;

    cudaFuncSetAttribute((const void*)gemm_mma_tf32<false, false>,
                         cudaFuncAttributeMaxDynamicSharedMemorySize, GEMM_SMEM_BYTES);
    cudaFuncSetAttribute((const void*)gemm_mma_tf32<true, false>,
                         cudaFuncAttributeMaxDynamicSharedMemorySize, GEMM_SMEM_BYTES);
    cudaFuncSetAttribute((const void*)gemm_mma_tf32<false, true>,
                         cudaFuncAttributeMaxDynamicSharedMemorySize, GEMM_SMEM_BYTES);
    cudaFuncSetAttribute((const void*)attn_kernel,
                         cudaFuncAttributeMaxDynamicSharedMemorySize, ATTN_SMEM_BYTES);

    float *pq, *pk, *pv, *pa, *pxr, *pwr;
    cudaGetSymbolAddress((void**)&pq,  g_q);
    cudaGetSymbolAddress((void**)&pk,  g_k);
    cudaGetSymbolAddress((void**)&pv,  g_v);
    cudaGetSymbolAddress((void**)&pa,  g_attn);
    cudaGetSymbolAddress((void**)&pxr, g_xr);
    cudaGetSymbolAddress((void**)&pwr, g_wr4);

    const dim3 ggrid(DIM / 128, MROWS / 128);     // (16, 32)
    const int RND_X = (MROWS * DIM / 4) / 256;    // 8192 blocks
    const int RND_W4 = (4 * DIM * DIM / 4) / 256; // 16384 blocks
    const size_t WSZ = (size_t)DIM * DIM;

    // pre-round operands to tf32-representable fp32 (RN)
    round_tf32_kernel<<<RND_X, 256>>>(x, pxr);
    round4_w_kernel<<<RND_W4, 256>>>(Wq, Wk, Wv, Wo, pwr);

    gemm_mma_tf32<false, false><<<ggrid, 128, GEMM_SMEM_BYTES>>>(pxr, pwr,           pq,  nullptr);
    gemm_mma_tf32<false, false><<<ggrid, 128, GEMM_SMEM_BYTES>>>(pxr, pwr + WSZ,     pk,  nullptr);
    gemm_mma_tf32<true,  false><<<ggrid, 128, GEMM_SMEM_BYTES>>>(pxr, pwr + 2 * WSZ, pv,  nullptr); // V rounded

    rmsnorm_rope_kernel<<<dim3(MROWS, 2), 256>>>(pq, pk, gq, gk, freqs);   // rounds q,k

    attn_kernel<<<dim3(SEQ / BLKQ, HEADS, BATCH), 256, ATTN_SMEM_BYTES>>>(seq_lens);
    // attention output is already tf32-rounded

    gemm_mma_tf32<false, true><<<ggrid, 128, GEMM_SMEM_BYTES>>>(pa, pwr + 3 * WSZ, out, bo);
}

// round 14
// speedup vs baseline: 3.6417x; 1.1477x over previous
#include <cuda_runtime.h>
#include <mma.h>
#include <math.h>
#include <cstdint>

#define DIM    2048
#define SEQ    2048
#define BATCH  2
#define HEADS  16
#define HDIM   128
#define MROWS  (BATCH*SEQ)   /* 4096 */
#define NM16   (MROWS/16)    /* 256 m16 blocks  */
#define NK8    (DIM/8)       /* 256 k8 blocks   */
#define NN8    (DIM/8)       /* 256 n8 blocks   */
#define NK16   (DIM/16)      /* 128 k16 blocks  */

// ---------------- scratch (device globals; no allocations) ----------------
__device__ float g_q[(size_t)MROWS * DIM];
__device__ float g_k[(size_t)MROWS * DIM];
__device__ float g_v[(size_t)MROWS * DIM];
__device__ float g_attn[(size_t)MROWS * DIM];
__device__ float g_xr[(size_t)MROWS * DIM];      // fragment-packed A operand
__device__ float g_wr4[(size_t)4 * DIM * DIM];   // fragment-packed Wq|Wk|Wv|Wo

// ---------------- cp.async helpers ----------------
__device__ __forceinline__ void cp_async16(void* dst, const void* src) {
    unsigned d = (unsigned)__cvta_generic_to_shared(dst);
    asm volatile("cp.async.cg.shared.global [%0], [%1], 16;\n" :: "r"(d), "l"(src));
}
#define CP_COMMIT() asm volatile("cp.async.commit_group;\n" ::: "memory")
#define CP_WAIT(n)  asm volatile("cp.async.wait_group %0;\n" :: "n"(n) : "memory")

// ---------------- raw tf32 mma (m16n8k8, row.col, fp32 accum) ----------------
__device__ __forceinline__ void mma_tf32(float d[4], const uint32_t a[4],
                                         const uint32_t b[2]) {
    asm volatile(
        "mma.sync.aligned.m16n8k8.row.col.f32.tf32.tf32.f32 "
        "{%0,%1,%2,%3}, {%4,%5,%6,%7}, {%8,%9}, {%0,%1,%2,%3};\n"
        : "+f"(d[0]), "+f"(d[1]), "+f"(d[2]), "+f"(d[3])
        : "r"(a[0]), "r"(a[1]), "r"(a[2]), "r"(a[3]), "r"(b[0]), "r"(b[1]));
}
__device__ __forceinline__ uint32_t f2u(float f) { return __float_as_uint(f); }
__device__ __forceinline__ float rtf32(float f) { return nvcuda::wmma::__float_to_tf32(f); }

// ============================================================================
// Repack A (row-major [M][2048]) -> fragment-packed PA[k8][m16][128] + rtf32.
// PA block (k8,m16), float f = lane*4+r:
//   value = A[m16*16 + (lane>>2) + 8*(r&1)][k8*8 + (lane&3) + 4*(r>>1)]
// CTA: 64 rows x 32 cols tile via smem; fully coalesced gmem both ways.
// ============================================================================
__global__ __launch_bounds__(256) void repack_a_kernel(
    const float* __restrict__ src, float* __restrict__ dst)
{
    __shared__ float ts[64][33];
    const int bx = blockIdx.x;     // k-tile (32 cols)  -> k8 blocks bx*4..+3
    const int by = blockIdx.y;     // row-tile (64 rows)-> m16 blocks by*4..+3
    const int tid = threadIdx.x;

#pragma unroll
    for (int i = 0; i < 2; i++) {
        int idx = tid + i * 256;            // 0..511 float4 slots
        int row = idx >> 3, c4 = (idx & 7) << 2;
        float4 v = *(const float4*)&src[(size_t)(by * 64 + row) * DIM + bx * 32 + c4];
        ts[row][c4 + 0] = rtf32(v.x); ts[row][c4 + 1] = rtf32(v.y);
        ts[row][c4 + 2] = rtf32(v.z); ts[row][c4 + 3] = rtf32(v.w);
    }
    __syncthreads();

#pragma unroll
    for (int i = 0; i < 8; i++) {
        int o = tid + i * 256;              // 0..2047
        int b = o >> 7, f = o & 127;
        int k8rel = b >> 2, m16rel = b & 3;
        int lane = f >> 2, r = f & 3;
        int row = m16rel * 16 + (lane >> 2) + ((r & 1) << 3);
        int col = k8rel * 8 + (lane & 3) + ((r >> 1) << 2);
        dst[((size_t)(bx * 4 + k8rel) * NM16 + by * 4 + m16rel) * 128 + f] = ts[row][col];
    }
}

// ============================================================================
// Repack B (weights, row-major [N][2048]) -> PB[k16][n8][128] + rtf32.
// PB block (k16,n8), float f = lane*4+r:
//   value = B[n8*8 + (lane>>2)][k16*16 + (lane&3) + 4*r]
// z-dim selects one of the 4 weight matrices.
// ============================================================================
__global__ __launch_bounds__(256) void repack_b4_kernel(
    const float* __restrict__ w0, const float* __restrict__ w1,
    const float* __restrict__ w2, const float* __restrict__ w3,
    float* __restrict__ dst)
{
    __shared__ float ts[64][33];
    const int bx = blockIdx.x;     // k-tile (32 cols)  -> k16 blocks bx*2..+1
    const int by = blockIdx.y;     // n-tile (64 rows)  -> n8 blocks by*8..+7
    const int w  = blockIdx.z;
    const int tid = threadIdx.x;
    const float* src = (w == 0) ? w0 : (w == 1) ? w1 : (w == 2) ? w2 : w3;
    float* d = dst + (size_t)w * DIM * DIM;

#pragma unroll
    for (int i = 0; i < 2; i++) {
        int idx = tid + i * 256;
        int row = idx >> 3, c4 = (idx & 7) << 2;
        float4 v = *(const float4*)&src[(size_t)(by * 64 + row) * DIM + bx * 32 + c4];
        ts[row][c4 + 0] = rtf32(v.x); ts[row][c4 + 1] = rtf32(v.y);
        ts[row][c4 + 2] = rtf32(v.z); ts[row][c4 + 3] = rtf32(v.w);
    }
    __syncthreads();

#pragma unroll
    for (int i = 0; i < 8; i++) {
        int o = tid + i * 256;
        int b = o >> 7, f = o & 127;
        int k16rel = b >> 3, n8rel = b & 7;
        int lane = f >> 2, r = f & 3;
        int row = n8rel * 8 + (lane >> 2);
        int col = k16rel * 16 + (lane & 3) + (r << 2);
        d[((size_t)(bx * 2 + k16rel) * NN8 + by * 8 + n8rel) * 128 + f] = ts[row][col];
    }
}

// ============================================================================
// NT GEMM on fragment-packed operands: C[4096,2048] = A @ B^T
// A = PA[k8][m16][128], B = PB[k16][n8][128]. CTA 128x128, 4 warps 64x64.
// K-tile 32, 3-stage cp.async (pure linear copies). All operand LDS are .128.
// ============================================================================
#define GSTG 3
#define GSTAGE_F 4096                       /* floats per operand per stage */
#define GEMM_SMEM_BYTES (2 * GSTG * GSTAGE_F * 4)   /* 98304 */

template <bool ROUND_OUT, bool ADD_BIAS>
__global__ __launch_bounds__(128, 2) void gemm_mma_tf32(
    const float* __restrict__ A, const float* __restrict__ B,
    float* __restrict__ C, const float* __restrict__ bias)
{
    extern __shared__ float smg[];
    float* sA = smg;
    float* sB = smg + GSTG * GSTAGE_F;

    const int bm   = blockIdx.y * 128;
    const int bn   = blockIdx.x * 128;
    const int bm16 = blockIdx.y * 8;
    const int bn8  = blockIdx.x * 16;
    const int tid  = threadIdx.x;
    const int warp = tid >> 5;
    const int lane = tid & 31;
    const int g    = lane >> 2;
    const int tig  = lane & 3;
    const int wm = warp >> 1;          // 0..1 (64 rows)
    const int wn = warp & 1;           // 0..1 (64 cols)

    const int ntiles = DIM / 32;       // 64

    float acc[4][8][4];
#pragma unroll
    for (int i = 0; i < 4; i++)
#pragma unroll
        for (int j = 0; j < 8; j++)
#pragma unroll
            for (int t = 0; t < 4; t++) acc[i][j][t] = 0.f;

    auto issue_tile = [&](int t) {
        int s = t % GSTG;
        float* as = sA + s * GSTAGE_F;
        float* bs = sB + s * GSTAGE_F;
        // A: 1024 16B chunks: k8rel = c>>8, rem = c&255 (8 m16 blocks x 32)
#pragma unroll
        for (int i = 0; i < 8; i++) {
            int c = tid + i * 128;
            int k8rel = c >> 8, rem = c & 255;
            const float* gs = A + (((size_t)(t * 4 + k8rel) * NM16 + bm16) * 32 + rem) * 4;
            cp_async16(as + c * 4, gs);
        }
        // B: 1024 16B chunks: k16rel = c>>9, rem = c&511 (16 n8 blocks x 32)
#pragma unroll
        for (int i = 0; i < 8; i++) {
            int c = tid + i * 128;
            int k16rel = c >> 9, rem = c & 511;
            const float* gs = B + (((size_t)(t * 2 + k16rel) * NN8 + bn8) * 32 + rem) * 4;
            cp_async16(bs + c * 4, gs);
        }
    };

    issue_tile(0); CP_COMMIT();
    issue_tile(1); CP_COMMIT();

    for (int t = 0; t < ntiles; t++) {
        CP_WAIT(1);                 // tile t resident
        __syncthreads();            // also protects stage about to be overwritten
        if (t + 2 < ntiles) issue_tile(t + 2);
        CP_COMMIT();

        const float* as = sA + (t % GSTG) * GSTAGE_F;
        const float* bs = sB + (t % GSTG) * GSTAGE_F;

#pragma unroll
        for (int k16 = 0; k16 < 2; k16++) {
            // B frags for BOTH k-steps of this k16: 8 x LDS.128
            float4 bq[8];
#pragma unroll
            for (int j = 0; j < 8; j++)
                bq[j] = *(const float4*)&bs[(k16 * 16 + wn * 8 + j) * 128 + lane * 4];

#pragma unroll
            for (int odd = 0; odd < 2; odd++) {
                int kk8 = k16 * 2 + odd;
                // A frags: 4 x LDS.128 (regs already in mma order)
                float4 aq[4];
#pragma unroll
                for (int i = 0; i < 4; i++)
                    aq[i] = *(const float4*)&as[(kk8 * 8 + wm * 4 + i) * 128 + lane * 4];

#pragma unroll
                for (int i = 0; i < 4; i++) {
                    uint32_t af[4] = { f2u(aq[i].x), f2u(aq[i].y),
                                       f2u(aq[i].z), f2u(aq[i].w) };
#pragma unroll
                    for (int j = 0; j < 8; j++) {
                        uint32_t bf[2];
                        if (odd == 0) { bf[0] = f2u(bq[j].x); bf[1] = f2u(bq[j].y); }
                        else          { bf[0] = f2u(bq[j].z); bf[1] = f2u(bq[j].w); }
                        mma_tf32(acc[i][j], af, bf);
                    }
                }
            }
        }
    }

    // epilogue: float2 stores (row-major C)
#pragma unroll
    for (int i = 0; i < 4; i++) {
        size_t ra = (size_t)(bm + wm * 64 + i * 16 + g);
        size_t rb = ra + 8;
#pragma unroll
        for (int j = 0; j < 8; j++) {
            size_t c = (size_t)(bn + wn * 64 + j * 8 + tig * 2);
            float b0 = 0.f, b1 = 0.f;
            if (ADD_BIAS) { b0 = bias[c]; b1 = bias[c + 1]; }
            float2 v0, v1;
            if (ROUND_OUT) {
                v0 = make_float2(rtf32(acc[i][j][0]), rtf32(acc[i][j][1]));
                v1 = make_float2(rtf32(acc[i][j][2]), rtf32(acc[i][j][3]));
            } else {
                v0 = make_float2(acc[i][j][0] + b0, acc[i][j][1] + b1);
                v1 = make_float2(acc[i][j][2] + b0, acc[i][j][3] + b1);
            }
            *(float2*)&C[ra * DIM + c] = v0;
            *(float2*)&C[rb * DIM + c] = v1;
        }
    }
}

// ============================================================================
// Fused RMSNorm (full dim=2048) + interleaved RoPE, in-place on q or k.
// Output rounded to tf32-representable fp32.
// ============================================================================
__global__ __launch_bounds__(256) void rmsnorm_rope_kernel(
    float* __restrict__ q, float* __restrict__ k,
    const float* __restrict__ gq, const float* __restrict__ gk,
    const float* __restrict__ freqs)
{
    float* x = (blockIdx.y == 0) ? q : k;
    const float* g = (blockIdx.y == 0) ? gq : gk;
    const int row = blockIdx.x;
    const int s   = row & (SEQ - 1);
    float* xr = x + (size_t)row * DIM;
    const int tid = threadIdx.x;

    float4 a = ((const float4*)xr)[tid];
    float4 b = ((const float4*)xr)[tid + 256];

    float ss = a.x*a.x + a.y*a.y + a.z*a.z + a.w*a.w
             + b.x*b.x + b.y*b.y + b.z*b.z + b.w*b.w;
#pragma unroll
    for (int o = 16; o > 0; o >>= 1)
        ss += __shfl_xor_sync(0xffffffffu, ss, o);

    __shared__ float red[8];
    if ((tid & 31) == 0) red[tid >> 5] = ss;
    __syncthreads();
    float tot = 0.f;
#pragma unroll
    for (int w = 0; w < 8; w++) tot += red[w];

    const float inv = rsqrtf(tot * (1.0f / (float)DIM) + 1e-6f);

    float4 ga = ((const float4*)g)[tid];
    float4 gb = ((const float4*)g)[tid + 256];
    const float* fr = freqs + (size_t)s * (HDIM / 2);

    {
        int p0 = 2 * tid, p1 = 2 * tid + 1;
        float s0, c0, s1, c1;
        sincosf(fr[p0 & 63], &s0, &c0);
        sincosf(fr[p1 & 63], &s1, &c1);
        float v0 = a.x * inv * ga.x, v1 = a.y * inv * ga.y;
        float v2 = a.z * inv * ga.z, v3 = a.w * inv * ga.w;
        float4 o;
        o.x = rtf32(v0 * c0 - v1 * s0);  o.y = rtf32(v0 * s0 + v1 * c0);
        o.z = rtf32(v2 * c1 - v3 * s1);  o.w = rtf32(v2 * s1 + v3 * c1);
        ((float4*)xr)[tid] = o;
    }
    {
        int p0 = 512 + 2 * tid, p1 = 513 + 2 * tid;
        float s0, c0, s1, c1;
        sincosf(fr[p0 & 63], &s0, &c0);
        sincosf(fr[p1 & 63], &s1, &c1);
        float v0 = b.x * inv * gb.x, v1 = b.y * inv * gb.y;
        float v2 = b.z * inv * gb.z, v3 = b.w * inv * gb.w;
        float4 o;
        o.x = rtf32(v0 * c0 - v1 * s0);  o.y = rtf32(v0 * s0 + v1 * c0);
        o.z = rtf32(v2 * c1 - v3 * s1);  o.w = rtf32(v2 * s1 + v3 * c1);
        ((float4*)xr)[tid + 256] = o;
    }
}

// ============================================================================
// Flash attention (varlen key mask), raw tf32 mma, O in registers.
// Unchanged from round 13 (passing). 128-query CTA tile, 256 threads.
// ============================================================================
#define BLKQ    128
#define SM_QS   0
#define SM_KS   16896
#define SM_VS   33792
#define SM_SS   42496
#define SM_M    51200   /* [128] */
#define SM_L    51328   /* [128] */
#define SM_RMAX 51456   /* [128][2] */
#define SM_RSUM 51712   /* [128][2] */
#define ATTN_SMEM_FLOATS 51968
#define ATTN_SMEM_BYTES  (ATTN_SMEM_FLOATS * 4)   /* 207872 */

__global__ __launch_bounds__(256) void attn_kernel(const int* __restrict__ seq_lens)
{
    extern __shared__ float sm[];
    float* Qs   = sm + SM_QS;
    float* Ks   = sm + SM_KS;
    float* Vs   = sm + SM_VS;
    float* Ss   = sm + SM_SS;
    float* mrow = sm + SM_M;
    float* lrow = sm + SM_L;
    float* rmax = sm + SM_RMAX;
    float* rsum = sm + SM_RSUM;

    const int b  = blockIdx.z;
    const int h  = blockIdx.y;
    const int q0 = blockIdx.x * BLKQ;
    const int seqlen = seq_lens[b];
    const int tid  = threadIdx.x;
    const int warp = tid >> 5;
    const int lane = tid & 31;
    const int g    = lane >> 2;
    const int tig  = lane & 3;
    const int wm = warp >> 1;          // 0..3 (32-query rows)
    const int wn = warp & 1;           // 0..1
    const float scale = 0.08838834764831845f;   // 1/sqrt(128)

    const int ntiles = (seqlen + 63) >> 6;

    auto issue_k = [&](int t) {
        float* ks = Ks + (t & 1) * 8448;
        int r0 = tid >> 5, c0 = (tid & 31) * 4;
#pragma unroll
        for (int i = 0; i < 8; i++) {
            int r = r0 + 8 * i;
            size_t base = (size_t)(b * SEQ + t * 64 + r) * DIM + h * HDIM + c0;
            cp_async16(&ks[r * 132 + c0], g_k + base);
        }
    };
    auto issue_v = [&](int t) {
        int r0 = tid >> 5, c0 = (tid & 31) * 4;
#pragma unroll
        for (int i = 0; i < 8; i++) {
            int r = r0 + 8 * i;
            size_t base = (size_t)(b * SEQ + t * 64 + r) * DIM + h * HDIM + c0;
            cp_async16(&Vs[r * 136 + c0], g_v + base);
        }
    };

    issue_k(0); CP_COMMIT();

#pragma unroll
    for (int i = 0; i < 16; i++) {
        int idx = tid + i * 256;
        int r = idx >> 5, c4 = idx & 31;
        const float* src = g_q + ((size_t)(b * SEQ + q0 + r) * DIM + h * HDIM + c4 * 4);
        *(float4*)&Qs[r * 132 + c4 * 4] = *(const float4*)src;
    }
    if (tid < BLKQ) { mrow[tid] = -1e30f; lrow[tid] = 0.f; }

    float oa[2][8][4];
#pragma unroll
    for (int i = 0; i < 2; i++)
#pragma unroll
        for (int j = 0; j < 8; j++)
#pragma unroll
            for (int u = 0; u < 4; u++) oa[i][j][u] = 0.f;

    for (int t = 0; t < ntiles; t++) {
        CP_WAIT(0);
        __syncthreads();                       // sync1
        issue_v(t); CP_COMMIT();
        if (t + 1 < ntiles) issue_k(t + 1);
        CP_COMMIT();

        const float* ks = Ks + (t & 1) * 8448;
        const int kv0 = t * 64;
        const int nvalid = seqlen - kv0;

        float sa[2][4][4];
#pragma unroll
        for (int i = 0; i < 2; i++)
#pragma unroll
            for (int j = 0; j < 4; j++)
#pragma unroll
                for (int u = 0; u < 4; u++) sa[i][j][u] = 0.f;

#pragma unroll
        for (int kk = 0; kk < HDIM; kk += 8) {
            uint32_t af[2][4];
#pragma unroll
            for (int i = 0; i < 2; i++) {
                const float* ap = &Qs[(wm * 32 + i * 16 + g) * 132 + kk + tig];
                af[i][0] = f2u(ap[0]);
                af[i][1] = f2u(ap[8 * 132]);
                af[i][2] = f2u(ap[4]);
                af[i][3] = f2u(ap[8 * 132 + 4]);
            }
            uint32_t bf[4][2];
#pragma unroll
            for (int j = 0; j < 4; j++) {
                const float* bp = &ks[(wn * 32 + j * 8 + g) * 132 + kk + tig];
                bf[j][0] = f2u(bp[0]);
                bf[j][1] = f2u(bp[4]);
            }
#pragma unroll
            for (int i = 0; i < 2; i++)
#pragma unroll
                for (int j = 0; j < 4; j++)
                    mma_tf32(sa[i][j], af[i], bf[j]);
        }

        float pmax[2][2];
#pragma unroll
        for (int i = 0; i < 2; i++)
#pragma unroll
            for (int hh = 0; hh < 2; hh++) pmax[i][hh] = -1e30f;
#pragma unroll
        for (int i = 0; i < 2; i++)
#pragma unroll
            for (int j = 0; j < 4; j++) {
                int cl = wn * 32 + j * 8 + tig * 2;
                bool v0 = cl < nvalid, v1 = (cl + 1) < nvalid;
#pragma unroll
                for (int u = 0; u < 4; u++) sa[i][j][u] *= scale;
                if (v0) { pmax[i][0] = fmaxf(pmax[i][0], sa[i][j][0]);
                          pmax[i][1] = fmaxf(pmax[i][1], sa[i][j][2]); }
                if (v1) { pmax[i][0] = fmaxf(pmax[i][0], sa[i][j][1]);
                          pmax[i][1] = fmaxf(pmax[i][1], sa[i][j][3]); }
            }
#pragma unroll
        for (int i = 0; i < 2; i++)
#pragma unroll
            for (int hh = 0; hh < 2; hh++) {
                float v = pmax[i][hh];
                v = fmaxf(v, __shfl_xor_sync(0xffffffffu, v, 1));
                v = fmaxf(v, __shfl_xor_sync(0xffffffffu, v, 2));
                pmax[i][hh] = v;
            }
        if (tig == 0) {
#pragma unroll
            for (int i = 0; i < 2; i++)
#pragma unroll
                for (int hh = 0; hh < 2; hh++)
                    rmax[(wm * 32 + i * 16 + g + hh * 8) * 2 + wn] = pmax[i][hh];
        }
        __syncthreads();                       // sync2

        float mnewr[2][2], rscr[2][2], psum[2][2];
#pragma unroll
        for (int i = 0; i < 2; i++)
#pragma unroll
            for (int hh = 0; hh < 2; hh++) {
                int r = wm * 32 + i * 16 + g + hh * 8;
                float vmax = fmaxf(rmax[r * 2 + 0], rmax[r * 2 + 1]);
                float mold = mrow[r];
                float mnew = fmaxf(mold, vmax);
                mnewr[i][hh] = mnew;
                rscr[i][hh]  = __expf(mold - mnew);
                psum[i][hh]  = 0.f;
            }
#pragma unroll
        for (int i = 0; i < 2; i++)
#pragma unroll
            for (int j = 0; j < 4; j++) {
                int cl = wn * 32 + j * 8 + tig * 2;
                bool v0 = cl < nvalid, v1 = (cl + 1) < nvalid;
                float p00 = v0 ? __expf(sa[i][j][0] - mnewr[i][0]) : 0.f;
                float p01 = v1 ? __expf(sa[i][j][1] - mnewr[i][0]) : 0.f;
                float p10 = v0 ? __expf(sa[i][j][2] - mnewr[i][1]) : 0.f;
                float p11 = v1 ? __expf(sa[i][j][3] - mnewr[i][1]) : 0.f;
                psum[i][0] += p00 + p01;
                psum[i][1] += p10 + p11;
                int r0 = wm * 32 + i * 16 + g;
                *(float2*)&Ss[r0 * 68 + cl]       = make_float2(rtf32(p00), rtf32(p01));
                *(float2*)&Ss[(r0 + 8) * 68 + cl] = make_float2(rtf32(p10), rtf32(p11));
            }
#pragma unroll
        for (int i = 0; i < 2; i++)
#pragma unroll
            for (int hh = 0; hh < 2; hh++) {
                float v = psum[i][hh];
                v += __shfl_xor_sync(0xffffffffu, v, 1);
                v += __shfl_xor_sync(0xffffffffu, v, 2);
                psum[i][hh] = v;
            }
        if (tig == 0) {
#pragma unroll
            for (int i = 0; i < 2; i++)
#pragma unroll
                for (int hh = 0; hh < 2; hh++)
                    rsum[(wm * 32 + i * 16 + g + hh * 8) * 2 + wn] = psum[i][hh];
        }
#pragma unroll
        for (int i = 0; i < 2; i++)
#pragma unroll
            for (int j = 0; j < 8; j++) {
                oa[i][j][0] *= rscr[i][0]; oa[i][j][1] *= rscr[i][0];
                oa[i][j][2] *= rscr[i][1]; oa[i][j][3] *= rscr[i][1];
            }
        CP_WAIT(1);                            // V(t) resident
        __syncthreads();                       // sync3

        if (wn == 0 && tig == 0) {
#pragma unroll
            for (int i = 0; i < 2; i++)
#pragma unroll
                for (int hh = 0; hh < 2; hh++) {
                    int r = wm * 32 + i * 16 + g + hh * 8;
                    float tot = rsum[r * 2 + 0] + rsum[r * 2 + 1];
                    lrow[r] = lrow[r] * rscr[i][hh] + tot;
                    mrow[r] = mnewr[i][hh];
                }
        }

#pragma unroll
        for (int kk = 0; kk < 64; kk += 8) {
            uint32_t af[2][4];
#pragma unroll
            for (int i = 0; i < 2; i++) {
                const float* ap = &Ss[(wm * 32 + i * 16 + g) * 68 + kk + tig];
                af[i][0] = f2u(ap[0]);
                af[i][1] = f2u(ap[8 * 68]);
                af[i][2] = f2u(ap[4]);
                af[i][3] = f2u(ap[8 * 68 + 4]);
            }
            uint32_t bf[8][2];
#pragma unroll
            for (int j = 0; j < 8; j++) {
                const float* bp = &Vs[(kk + tig) * 136 + wn * 64 + j * 8 + g];
                bf[j][0] = f2u(bp[0]);
                bf[j][1] = f2u(bp[4 * 136]);
            }
#pragma unroll
            for (int i = 0; i < 2; i++)
#pragma unroll
                for (int j = 0; j < 8; j++)
                    mma_tf32(oa[i][j], af[i], bf[j]);
        }
    }

    __syncthreads();

#pragma unroll
    for (int i = 0; i < 2; i++) {
        int r0 = wm * 32 + i * 16 + g;
        float invl0 = 1.0f / lrow[r0];
        float invl1 = 1.0f / lrow[r0 + 8];
        size_t row0 = (size_t)(b * SEQ + q0 + r0) * DIM + h * HDIM;
        size_t row1 = row0 + (size_t)8 * DIM;
#pragma unroll
        for (int j = 0; j < 8; j++) {
            int c = wn * 64 + j * 8 + tig * 2;
            *(float2*)&g_attn[row0 + c] =
                make_float2(rtf32(oa[i][j][0] * invl0), rtf32(oa[i][j][1] * invl0));
            *(float2*)&g_attn[row1 + c] =
                make_float2(rtf32(oa[i][j][2] * invl1), rtf32(oa[i][j][3] * invl1));
        }
    }
}

// ============================================================================
extern "C" void kernel_launch(void* const* d_in, const int* in_sizes, int n_in,
                              void* d_out, int out_size)
{
    const float* x        = (const float*)d_in[0];
    const int*   seq_lens = (const int*)d_in[1];
    /* d_in[2] grid_sizes (int64) — unused by reference */
    const float* freqs    = (const float*)d_in[3];
    const float* Wq       = (const float*)d_in[4];
    const float* Wk       = (const float*)d_in[5];
    const float* Wv       = (const float*)d_in[6];
    const float* Wo       = (const float*)d_in[7];
    const float* bo       = (const float*)d_in[8];
    const float* gq       = (const float*)d_in[9];
    const float* gk       = (const float*)d_in[10];
    float* out = (float*)d_out;

    cudaFuncSetAttribute((const void*)gemm_mma_tf32<false, false>,
                         cudaFuncAttributeMaxDynamicSharedMemorySize, GEMM_SMEM_BYTES);
    cudaFuncSetAttribute((const void*)gemm_mma_tf32<true, false>,
                         cudaFuncAttributeMaxDynamicSharedMemorySize, GEMM_SMEM_BYTES);
    cudaFuncSetAttribute((const void*)gemm_mma_tf32<false, true>,
                         cudaFuncAttributeMaxDynamicSharedMemorySize, GEMM_SMEM_BYTES);
    cudaFuncSetAttribute((const void*)attn_kernel,
                         cudaFuncAttributeMaxDynamicSharedMemorySize, ATTN_SMEM_BYTES);

    float *pq, *pk, *pv, *pa, *pxr, *pwr;
    cudaGetSymbolAddress((void**)&pq,  g_q);
    cudaGetSymbolAddress((void**)&pk,  g_k);
    cudaGetSymbolAddress((void**)&pv,  g_v);
    cudaGetSymbolAddress((void**)&pa,  g_attn);
    cudaGetSymbolAddress((void**)&pxr, g_xr);
    cudaGetSymbolAddress((void**)&pwr, g_wr4);

    const dim3 ggrid(DIM / 128, MROWS / 128);     // (16, 32)
    const size_t WSZ = (size_t)DIM * DIM;

    // fragment-pack (+ tf32-round) operands
    repack_a_kernel<<<dim3(DIM / 32, MROWS / 64), 256>>>(x, pxr);        // (64,64)
    repack_b4_kernel<<<dim3(DIM / 32, DIM / 64, 4), 256>>>(Wq, Wk, Wv, Wo, pwr);

    gemm_mma_tf32<false, false><<<ggrid, 128, GEMM_SMEM_BYTES>>>(pxr, pwr,           pq,  nullptr);
    gemm_mma_tf32<false, false><<<ggrid, 128, GEMM_SMEM_BYTES>>>(pxr, pwr + WSZ,     pk,  nullptr);
    gemm_mma_tf32<true,  false><<<ggrid, 128, GEMM_SMEM_BYTES>>>(pxr, pwr + 2 * WSZ, pv,  nullptr);

    rmsnorm_rope_kernel<<<dim3(MROWS, 2), 256>>>(pq, pk, gq, gk, freqs);

    attn_kernel<<<dim3(SEQ / BLKQ, HEADS, BATCH), 256, ATTN_SMEM_BYTES>>>(seq_lens);

    // repack attention output for the O-projection (g_xr is free now)
    repack_a_kernel<<<dim3(DIM / 32, MROWS / 64), 256>>>(pa, pxr);

    gemm_mma_tf32<false, true><<<ggrid, 128, GEMM_SMEM_BYTES>>>(pxr, pwr + 3 * WSZ, out, bo);
}

// round 15
// speedup vs baseline: 3.7130x; 1.0196x over previous
#include <cuda_runtime.h>
#include <mma.h>
#include <math.h>
#include <cstdint>

#define DIM    2048
#define SEQ    2048
#define BATCH  2
#define HEADS  16
#define HDIM   128
#define MROWS  (BATCH*SEQ)   /* 4096 */
#define NM16   (MROWS/16)    /* 256 m16 blocks  */
#define NN8    (DIM/8)       /* 256 n8 blocks   */

// ---------------- scratch (device globals; no allocations) ----------------
__device__ float g_q[(size_t)MROWS * DIM];       // Q proj, row-major (pre-rmsnorm)
__device__ float g_k[(size_t)MROWS * DIM];       // K proj, row-major (pre-rmsnorm)
__device__ float g_v[(size_t)MROWS * DIM];       // V packed B-frag per (b,h)
__device__ float g_attn[(size_t)MROWS * DIM];    // attention out, row-major
__device__ float g_xr[(size_t)MROWS * DIM];      // packed x / packed K / packed attn
__device__ float g_qp[(size_t)MROWS * DIM];      // packed Q (A-frag per b,h)
__device__ float g_wr4[(size_t)4 * DIM * DIM];   // packed Wq|Wk|Wv|Wo

// ---------------- cp.async helpers ----------------
__device__ __forceinline__ void cp_async16(void* dst, const void* src) {
    unsigned d = (unsigned)__cvta_generic_to_shared(dst);
    asm volatile("cp.async.cg.shared.global [%0], [%1], 16;\n" :: "r"(d), "l"(src));
}
#define CP_COMMIT() asm volatile("cp.async.commit_group;\n" ::: "memory")
#define CP_WAIT(n)  asm volatile("cp.async.wait_group %0;\n" :: "n"(n) : "memory")

// ---------------- raw tf32 mma (m16n8k8, row.col, fp32 accum) ----------------
__device__ __forceinline__ void mma_tf32(float d[4], const uint32_t a[4],
                                         const uint32_t b[2]) {
    asm volatile(
        "mma.sync.aligned.m16n8k8.row.col.f32.tf32.tf32.f32 "
        "{%0,%1,%2,%3}, {%4,%5,%6,%7}, {%8,%9}, {%0,%1,%2,%3};\n"
        : "+f"(d[0]), "+f"(d[1]), "+f"(d[2]), "+f"(d[3])
        : "r"(a[0]), "r"(a[1]), "r"(a[2]), "r"(a[3]), "r"(b[0]), "r"(b[1]));
}
__device__ __forceinline__ uint32_t f2u(float f) { return __float_as_uint(f); }
__device__ __forceinline__ float rtf32(float f) { return nvcuda::wmma::__float_to_tf32(f); }

// ============================================================================
// Repack A (row-major [M][2048]) -> PA[k8][m16][128] + rtf32.
//   PA(k8,m16), f = lane*4+r: A[m16*16 + (lane>>2) + 8*(r&1)][k8*8 + (lane&3) + 4*(r>>1)]
// ============================================================================
__global__ __launch_bounds__(256) void repack_a_kernel(
    const float* __restrict__ src, float* __restrict__ dst)
{
    __shared__ float ts[64][33];
    const int bx = blockIdx.x;     // k-tile (32 cols)  -> k8 blocks bx*4..+3
    const int by = blockIdx.y;     // row-tile (64 rows)-> m16 blocks by*4..+3
    const int tid = threadIdx.x;

#pragma unroll
    for (int i = 0; i < 2; i++) {
        int idx = tid + i * 256;
        int row = idx >> 3, c4 = (idx & 7) << 2;
        float4 v = *(const float4*)&src[(size_t)(by * 64 + row) * DIM + bx * 32 + c4];
        ts[row][c4 + 0] = rtf32(v.x); ts[row][c4 + 1] = rtf32(v.y);
        ts[row][c4 + 2] = rtf32(v.z); ts[row][c4 + 3] = rtf32(v.w);
    }
    __syncthreads();

#pragma unroll
    for (int i = 0; i < 8; i++) {
        int o = tid + i * 256;
        int b = o >> 7, f = o & 127;
        int k8rel = b >> 2, m16rel = b & 3;
        int lane = f >> 2, r = f & 3;
        int row = m16rel * 16 + (lane >> 2) + ((r & 1) << 3);
        int col = k8rel * 8 + (lane & 3) + ((r >> 1) << 2);
        dst[((size_t)(bx * 4 + k8rel) * NM16 + by * 4 + m16rel) * 128 + f] = ts[row][col];
    }
}

// ============================================================================
// Repack B (weights [N][2048]) -> PB[k16][n8][128] + rtf32.
//   PB(k16,n8), f = lane*4+r: B[n8*8 + (lane>>2)][k16*16 + (lane&3) + 4r]
// ============================================================================
__global__ __launch_bounds__(256) void repack_b4_kernel(
    const float* __restrict__ w0, const float* __restrict__ w1,
    const float* __restrict__ w2, const float* __restrict__ w3,
    float* __restrict__ dst)
{
    __shared__ float ts[64][33];
    const int bx = blockIdx.x;
    const int by = blockIdx.y;
    const int w  = blockIdx.z;
    const int tid = threadIdx.x;
    const float* src = (w == 0) ? w0 : (w == 1) ? w1 : (w == 2) ? w2 : w3;
    float* d = dst + (size_t)w * DIM * DIM;

#pragma unroll
    for (int i = 0; i < 2; i++) {
        int idx = tid + i * 256;
        int row = idx >> 3, c4 = (idx & 7) << 2;
        float4 v = *(const float4*)&src[(size_t)(by * 64 + row) * DIM + bx * 32 + c4];
        ts[row][c4 + 0] = rtf32(v.x); ts[row][c4 + 1] = rtf32(v.y);
        ts[row][c4 + 2] = rtf32(v.z); ts[row][c4 + 3] = rtf32(v.w);
    }
    __syncthreads();

#pragma unroll
    for (int i = 0; i < 8; i++) {
        int o = tid + i * 256;
        int b = o >> 7, f = o & 127;
        int k16rel = b >> 3, n8rel = b & 7;
        int lane = f >> 2, r = f & 3;
        int row = n8rel * 8 + (lane >> 2);
        int col = k16rel * 16 + (lane & 3) + (r << 2);
        d[((size_t)(bx * 2 + k16rel) * NN8 + by * 8 + n8rel) * 128 + f] = ts[row][col];
    }
}

// ============================================================================
// NT GEMM on fragment-packed operands. CTA 128x128, 4 warps 64x64, K-tile 32,
// 3-stage cp.async. PACK_V: epilogue writes V in packed B-frag layout per (b,h).
// ============================================================================
#define GSTG 3
#define GSTAGE_F 4096
#define GEMM_SMEM_BYTES (2 * GSTG * GSTAGE_F * 4)   /* 98304 */

template <bool ADD_BIAS, bool PACK_V>
__global__ __launch_bounds__(128, 2) void gemm_mma_tf32(
    const float* __restrict__ A, const float* __restrict__ B,
    float* __restrict__ C, const float* __restrict__ bias)
{
    extern __shared__ float smg[];
    float* sA = smg;
    float* sB = smg + GSTG * GSTAGE_F;

    const int bm   = blockIdx.y * 128;
    const int bn   = blockIdx.x * 128;
    const int bm16 = blockIdx.y * 8;
    const int bn8  = blockIdx.x * 16;
    const int tid  = threadIdx.x;
    const int warp = tid >> 5;
    const int lane = tid & 31;
    const int g    = lane >> 2;
    const int tig  = lane & 3;
    const int wm = warp >> 1;
    const int wn = warp & 1;

    const int ntiles = DIM / 32;

    float acc[4][8][4];
#pragma unroll
    for (int i = 0; i < 4; i++)
#pragma unroll
        for (int j = 0; j < 8; j++)
#pragma unroll
            for (int t = 0; t < 4; t++) acc[i][j][t] = 0.f;

    auto issue_tile = [&](int t) {
        int s = t % GSTG;
        float* as = sA + s * GSTAGE_F;
        float* bs = sB + s * GSTAGE_F;
#pragma unroll
        for (int i = 0; i < 8; i++) {
            int c = tid + i * 128;
            int k8rel = c >> 8, rem = c & 255;
            const float* gs = A + (((size_t)(t * 4 + k8rel) * NM16 + bm16) * 32 + rem) * 4;
            cp_async16(as + c * 4, gs);
        }
#pragma unroll
        for (int i = 0; i < 8; i++) {
            int c = tid + i * 128;
            int k16rel = c >> 9, rem = c & 511;
            const float* gs = B + (((size_t)(t * 2 + k16rel) * NN8 + bn8) * 32 + rem) * 4;
            cp_async16(bs + c * 4, gs);
        }
    };

    issue_tile(0); CP_COMMIT();
    issue_tile(1); CP_COMMIT();

    for (int t = 0; t < ntiles; t++) {
        CP_WAIT(1);
        __syncthreads();
        if (t + 2 < ntiles) issue_tile(t + 2);
        CP_COMMIT();

        const float* as = sA + (t % GSTG) * GSTAGE_F;
        const float* bs = sB + (t % GSTG) * GSTAGE_F;

#pragma unroll
        for (int k16 = 0; k16 < 2; k16++) {
            float4 bq[8];
#pragma unroll
            for (int j = 0; j < 8; j++)
                bq[j] = *(const float4*)&bs[(k16 * 16 + wn * 8 + j) * 128 + lane * 4];

#pragma unroll
            for (int odd = 0; odd < 2; odd++) {
                int kk8 = k16 * 2 + odd;
                float4 aq[4];
#pragma unroll
                for (int i = 0; i < 4; i++)
                    aq[i] = *(const float4*)&as[(kk8 * 8 + wm * 4 + i) * 128 + lane * 4];

#pragma unroll
                for (int i = 0; i < 4; i++) {
                    uint32_t af[4] = { f2u(aq[i].x), f2u(aq[i].y),
                                       f2u(aq[i].z), f2u(aq[i].w) };
#pragma unroll
                    for (int j = 0; j < 8; j++) {
                        uint32_t bf[2];
                        if (odd == 0) { bf[0] = f2u(bq[j].x); bf[1] = f2u(bq[j].y); }
                        else          { bf[0] = f2u(bq[j].z); bf[1] = f2u(bq[j].w); }
                        mma_tf32(acc[i][j], af, bf);
                    }
                }
            }
        }
    }

    if (PACK_V) {
        // V packed B-frag per (b,h): idx = (((b*16+h)*128 + s/16)*16 + n8)*128
        //                                  + (nl&7)*16 + (s&3)*4 + ((s>>2)&3)
#pragma unroll
        for (int i = 0; i < 4; i++) {
#pragma unroll
            for (int hh = 0; hh < 2; hh++) {
                int R = bm + wm * 64 + i * 16 + g + hh * 8;
                int b = R >> 11, s = R & 2047;
                size_t rowbase = ((size_t)(b * 16) * 128 + (s >> 4)) * 2048;
                int soff = (s & 3) * 4 + ((s >> 2) & 3);
#pragma unroll
                for (int j = 0; j < 8; j++) {
                    int c0 = bn + wn * 64 + j * 8 + tig * 2;
#pragma unroll
                    for (int e = 0; e < 2; e++) {
                        int C2 = c0 + e;
                        int h = C2 >> 7, nl = C2 & 127;
                        size_t idx = rowbase + (size_t)h * 128 * 2048
                                   + ((nl >> 3) * 128 + (nl & 7) * 16 + soff);
                        C[idx] = rtf32(acc[i][j][e + 2 * hh]);
                    }
                }
            }
        }
    } else {
#pragma unroll
        for (int i = 0; i < 4; i++) {
            size_t ra = (size_t)(bm + wm * 64 + i * 16 + g);
            size_t rb = ra + 8;
#pragma unroll
            for (int j = 0; j < 8; j++) {
                size_t c = (size_t)(bn + wn * 64 + j * 8 + tig * 2);
                float b0 = 0.f, b1 = 0.f;
                if (ADD_BIAS) { b0 = bias[c]; b1 = bias[c + 1]; }
                *(float2*)&C[ra * DIM + c] =
                    make_float2(acc[i][j][0] + b0, acc[i][j][1] + b1);
                *(float2*)&C[rb * DIM + c] =
                    make_float2(acc[i][j][2] + b0, acc[i][j][3] + b1);
            }
        }
    }
}

// ============================================================================
// Fused RMSNorm + RoPE; writes q in packed A-frag (g_qp), k in packed B-frag
// (g_xr), per (b, head). Values identical to before (rtf32-rounded).
// ============================================================================
__global__ __launch_bounds__(256) void rmsnorm_rope_kernel(
    const float* __restrict__ q, const float* __restrict__ k,
    float* __restrict__ qp, float* __restrict__ kp,
    const float* __restrict__ gq, const float* __restrict__ gk,
    const float* __restrict__ freqs)
{
    const int isq = (blockIdx.y == 0);
    const float* x = isq ? q : k;
    const float* g = isq ? gq : gk;
    const int row = blockIdx.x;
    const int b   = row >> 11;
    const int s   = row & (SEQ - 1);
    const float* xr = x + (size_t)row * DIM;
    const int tid = threadIdx.x;

    float4 a = ((const float4*)xr)[tid];
    float4 bb = ((const float4*)xr)[tid + 256];

    float ss = a.x*a.x + a.y*a.y + a.z*a.z + a.w*a.w
             + bb.x*bb.x + bb.y*bb.y + bb.z*bb.z + bb.w*bb.w;
#pragma unroll
    for (int o = 16; o > 0; o >>= 1)
        ss += __shfl_xor_sync(0xffffffffu, ss, o);

    __shared__ float red[8];
    if ((tid & 31) == 0) red[tid >> 5] = ss;
    __syncthreads();
    float tot = 0.f;
#pragma unroll
    for (int w = 0; w < 8; w++) tot += red[w];

    const float inv = rsqrtf(tot * (1.0f / (float)DIM) + 1e-6f);

    float4 ga = ((const float4*)g)[tid];
    float4 gb = ((const float4*)g)[tid + 256];
    const float* fr = freqs + (size_t)s * (HDIM / 2);

    // packed writers
    auto store_packed = [&](int D, float val) {
        int h = D >> 7;
        if (isq) {
            int k8 = (D >> 3) & 15, d = D & 7;
            size_t idx = (((size_t)(b * 16 + h) * 16 + k8) * 128 + (s >> 4)) * 128
                       + ((s & 7) * 4 + (d & 3)) * 4 + ((s >> 3) & 1) + 2 * (d >> 2);
            qp[idx] = val;
        } else {
            int k16 = (D >> 4) & 7, e16 = D & 15;
            size_t idx = (((size_t)(b * 16 + h) * 8 + k16) * 256 + (s >> 3)) * 128
                       + ((s & 7) * 4 + (e16 & 3)) * 4 + (e16 >> 2);
            kp[idx] = val;
        }
    };

    {
        int p0 = 2 * tid, p1 = 2 * tid + 1;
        float s0, c0, s1, c1;
        sincosf(fr[p0 & 63], &s0, &c0);
        sincosf(fr[p1 & 63], &s1, &c1);
        float v0 = a.x * inv * ga.x, v1 = a.y * inv * ga.y;
        float v2 = a.z * inv * ga.z, v3 = a.w * inv * ga.w;
        int D = 4 * tid;
        store_packed(D + 0, rtf32(v0 * c0 - v1 * s0));
        store_packed(D + 1, rtf32(v0 * s0 + v1 * c0));
        store_packed(D + 2, rtf32(v2 * c1 - v3 * s1));
        store_packed(D + 3, rtf32(v2 * s1 + v3 * c1));
    }
    {
        int p0 = 512 + 2 * tid, p1 = 513 + 2 * tid;
        float s0, c0, s1, c1;
        sincosf(fr[p0 & 63], &s0, &c0);
        sincosf(fr[p1 & 63], &s1, &c1);
        float v0 = bb.x * inv * gb.x, v1 = bb.y * inv * gb.y;
        float v2 = bb.z * inv * gb.z, v3 = bb.w * inv * gb.w;
        int D = 1024 + 4 * tid;
        store_packed(D + 0, rtf32(v0 * c0 - v1 * s0));
        store_packed(D + 1, rtf32(v0 * s0 + v1 * c0));
        store_packed(D + 2, rtf32(v2 * c1 - v3 * s1));
        store_packed(D + 3, rtf32(v2 * s1 + v3 * c1));
    }
}

// ============================================================================
// Flash attention: all operands fragment-packed -> LDS.128 everywhere.
// CTA = (b, h, 128 queries), 256 threads. K double-buffered, V single (own
// cp.async group). smem: Qs[16][8][128] | Ks 2x[8][8][128] | Vs[4][16][128]
// | Ss[8][8][128] | m/l/rmax/rsum
// ============================================================================
#define BLKQ    128
#define SM_QS   0
#define SM_KS   16384
#define SM_VS   32768
#define SM_SS   40960
#define SM_M    49152
#define SM_L    49280
#define SM_RMAX 49408   /* [128][2] */
#define SM_RSUM 49664   /* [128][2] */
#define ATTN_SMEM_FLOATS 49920
#define ATTN_SMEM_BYTES  (ATTN_SMEM_FLOATS * 4)   /* 199680 */

__global__ __launch_bounds__(256) void attn_kernel(
    const int* __restrict__ seq_lens,
    const float* __restrict__ qp, const float* __restrict__ kp,
    const float* __restrict__ vp)
{
    extern __shared__ float sm[];
    float* Qs   = sm + SM_QS;
    float* Ks   = sm + SM_KS;
    float* Vs   = sm + SM_VS;
    float* Ss   = sm + SM_SS;
    float* mrow = sm + SM_M;
    float* lrow = sm + SM_L;
    float* rmax = sm + SM_RMAX;
    float* rsum = sm + SM_RSUM;

    const int b  = blockIdx.z;
    const int h  = blockIdx.y;
    const int q0 = blockIdx.x * BLKQ;
    const int q016 = q0 >> 4;
    const int seqlen = seq_lens[b];
    const int tid  = threadIdx.x;
    const int warp = tid >> 5;
    const int lane = tid & 31;
    const int g    = lane >> 2;
    const int tig  = lane & 3;
    const int wm = warp >> 1;          // 0..3
    const int wn = warp & 1;           // 0..1
    const float scale = 0.08838834764831845f;

    const int bh = b * 16 + h;
    const int ntiles = (seqlen + 63) >> 6;

    auto issue_k = [&](int t) {
        float* ks = Ks + (t & 1) * 8192;
#pragma unroll
        for (int i = 0; i < 8; i++) {
            int c = tid + i * 256;                 // 0..2047
            int k16 = c >> 8, n8rel = (c >> 5) & 7, w = c & 31;
            const float* gs = kp + ((((size_t)bh * 8 + k16) * 256 + t * 8 + n8rel) * 128 + w * 4);
            cp_async16(&ks[(k16 * 8 + n8rel) * 128 + w * 4], gs);
        }
    };
    auto issue_v = [&](int t) {
#pragma unroll
        for (int i = 0; i < 8; i++) {
            int c = tid + i * 256;                 // 0..2047
            int k16rel = c >> 9, n8 = (c >> 5) & 15, w = c & 31;
            const float* gs = vp + ((((size_t)bh * 128 + t * 4 + k16rel) * 16 + n8) * 128 + w * 4);
            cp_async16(&Vs[(k16rel * 16 + n8) * 128 + w * 4], gs);
        }
    };

    issue_k(0); CP_COMMIT();

    // load packed Q (linear float4)
#pragma unroll
    for (int i = 0; i < 16; i++) {
        int idx = tid + i * 256;                   // 0..4095 float4 slots
        int k8 = idx >> 8, m16rel = (idx >> 5) & 7, w = idx & 31;
        const float4* src = (const float4*)(qp
            + ((((size_t)bh * 16 + k8) * 128 + q016 + m16rel) * 128 + w * 4));
        *(float4*)&Qs[(k8 * 8 + m16rel) * 128 + w * 4] = *src;
    }
    if (tid < BLKQ) { mrow[tid] = -1e30f; lrow[tid] = 0.f; }

    float oa[2][8][4];
#pragma unroll
    for (int i = 0; i < 2; i++)
#pragma unroll
        for (int j = 0; j < 8; j++)
#pragma unroll
            for (int u = 0; u < 4; u++) oa[i][j][u] = 0.f;

    for (int t = 0; t < ntiles; t++) {
        CP_WAIT(0);
        __syncthreads();                           // sync1: K(t) resident
        issue_v(t); CP_COMMIT();                   // group: V(t)
        if (t + 1 < ntiles) issue_k(t + 1);
        CP_COMMIT();                               // group: K(t+1)

        const float* ks = Ks + (t & 1) * 8192;
        const int kv0 = t * 64;
        const int nvalid = seqlen - kv0;

        // ---- S = scale * Q @ K^T (128x64); warp tile 32x32 ----
        float sa[2][4][4];
#pragma unroll
        for (int i = 0; i < 2; i++)
#pragma unroll
            for (int j = 0; j < 4; j++)
#pragma unroll
                for (int u = 0; u < 4; u++) sa[i][j][u] = 0.f;

#pragma unroll
        for (int k16 = 0; k16 < 8; k16++) {
            float4 bq[4];
#pragma unroll
            for (int j = 0; j < 4; j++)
                bq[j] = *(const float4*)&ks[(k16 * 8 + wn * 4 + j) * 128 + lane * 4];
#pragma unroll
            for (int odd = 0; odd < 2; odd++) {
                int kk8 = k16 * 2 + odd;
                float4 aq[2];
#pragma unroll
                for (int i = 0; i < 2; i++)
                    aq[i] = *(const float4*)&Qs[(kk8 * 8 + wm * 2 + i) * 128 + lane * 4];
#pragma unroll
                for (int i = 0; i < 2; i++) {
                    uint32_t af[4] = { f2u(aq[i].x), f2u(aq[i].y),
                                       f2u(aq[i].z), f2u(aq[i].w) };
#pragma unroll
                    for (int j = 0; j < 4; j++) {
                        uint32_t bf[2];
                        if (odd == 0) { bf[0] = f2u(bq[j].x); bf[1] = f2u(bq[j].y); }
                        else          { bf[0] = f2u(bq[j].z); bf[1] = f2u(bq[j].w); }
                        mma_tf32(sa[i][j], af, bf);
                    }
                }
            }
        }

        // ---- masked row maxes -> rmax ----
        float pmax[2][2];
#pragma unroll
        for (int i = 0; i < 2; i++)
#pragma unroll
            for (int hh = 0; hh < 2; hh++) pmax[i][hh] = -1e30f;
#pragma unroll
        for (int i = 0; i < 2; i++)
#pragma unroll
            for (int j = 0; j < 4; j++) {
                int cl = wn * 32 + j * 8 + tig * 2;
                bool v0 = cl < nvalid, v1 = (cl + 1) < nvalid;
#pragma unroll
                for (int u = 0; u < 4; u++) sa[i][j][u] *= scale;
                if (v0) { pmax[i][0] = fmaxf(pmax[i][0], sa[i][j][0]);
                          pmax[i][1] = fmaxf(pmax[i][1], sa[i][j][2]); }
                if (v1) { pmax[i][0] = fmaxf(pmax[i][0], sa[i][j][1]);
                          pmax[i][1] = fmaxf(pmax[i][1], sa[i][j][3]); }
            }
#pragma unroll
        for (int i = 0; i < 2; i++)
#pragma unroll
            for (int hh = 0; hh < 2; hh++) {
                float v = pmax[i][hh];
                v = fmaxf(v, __shfl_xor_sync(0xffffffffu, v, 1));
                v = fmaxf(v, __shfl_xor_sync(0xffffffffu, v, 2));
                pmax[i][hh] = v;
            }
        if (tig == 0) {
#pragma unroll
            for (int i = 0; i < 2; i++)
#pragma unroll
                for (int hh = 0; hh < 2; hh++)
                    rmax[(wm * 32 + i * 16 + g + hh * 8) * 2 + wn] = pmax[i][hh];
        }
        __syncthreads();                           // sync2

        // ---- exp + store P (packed A-frag layout) + partial sums ----
        float mnewr[2][2], rscr[2][2], psum[2][2];
#pragma unroll
        for (int i = 0; i < 2; i++)
#pragma unroll
            for (int hh = 0; hh < 2; hh++) {
                int r = wm * 32 + i * 16 + g + hh * 8;
                float vmax = fmaxf(rmax[r * 2 + 0], rmax[r * 2 + 1]);
                float mold = mrow[r];
                float mnew = fmaxf(mold, vmax);
                mnewr[i][hh] = mnew;
                rscr[i][hh]  = __expf(mold - mnew);
                psum[i][hh]  = 0.f;
            }
        const int c3  = (tig * 2) & 3;             // 0 or 2
        const int cb2 = (tig >> 1) * 2;            // r contribution of col bit
#pragma unroll
        for (int i = 0; i < 2; i++) {
            int m16rel = wm * 2 + i;
#pragma unroll
            for (int j = 0; j < 4; j++) {
                int cl = wn * 32 + j * 8 + tig * 2;
                bool v0 = cl < nvalid, v1 = (cl + 1) < nvalid;
                float p00 = v0 ? __expf(sa[i][j][0] - mnewr[i][0]) : 0.f;
                float p01 = v1 ? __expf(sa[i][j][1] - mnewr[i][0]) : 0.f;
                float p10 = v0 ? __expf(sa[i][j][2] - mnewr[i][1]) : 0.f;
                float p11 = v1 ? __expf(sa[i][j][3] - mnewr[i][1]) : 0.f;
                psum[i][0] += p00 + p01;
                psum[i][1] += p10 + p11;
                int base = ((wn * 4 + j) * 8 + m16rel) * 128 + g * 16;
                Ss[base + c3 * 4 + cb2 + 0]       = rtf32(p00);
                Ss[base + (c3 + 1) * 4 + cb2 + 0] = rtf32(p01);
                Ss[base + c3 * 4 + cb2 + 1]       = rtf32(p10);
                Ss[base + (c3 + 1) * 4 + cb2 + 1] = rtf32(p11);
            }
        }
#pragma unroll
        for (int i = 0; i < 2; i++)
#pragma unroll
            for (int hh = 0; hh < 2; hh++) {
                float v = psum[i][hh];
                v += __shfl_xor_sync(0xffffffffu, v, 1);
                v += __shfl_xor_sync(0xffffffffu, v, 2);
                psum[i][hh] = v;
            }
        if (tig == 0) {
#pragma unroll
            for (int i = 0; i < 2; i++)
#pragma unroll
                for (int hh = 0; hh < 2; hh++)
                    rsum[(wm * 32 + i * 16 + g + hh * 8) * 2 + wn] = psum[i][hh];
        }
#pragma unroll
        for (int i = 0; i < 2; i++)
#pragma unroll
            for (int j = 0; j < 8; j++) {
                oa[i][j][0] *= rscr[i][0]; oa[i][j][1] *= rscr[i][0];
                oa[i][j][2] *= rscr[i][1]; oa[i][j][3] *= rscr[i][1];
            }
        CP_WAIT(1);                                // V(t) resident
        __syncthreads();                           // sync3

        if (wn == 0 && tig == 0) {
#pragma unroll
            for (int i = 0; i < 2; i++)
#pragma unroll
                for (int hh = 0; hh < 2; hh++) {
                    int r = wm * 32 + i * 16 + g + hh * 8;
                    float tot = rsum[r * 2 + 0] + rsum[r * 2 + 1];
                    lrow[r] = lrow[r] * rscr[i][hh] + tot;
                    mrow[r] = mnewr[i][hh];
                }
        }

        // ---- O += P @ V (128x128); warp tile 32x64; all LDS.128 ----
#pragma unroll
        for (int k16r = 0; k16r < 4; k16r++) {
            float4 bq[8];
#pragma unroll
            for (int j = 0; j < 8; j++)
                bq[j] = *(const float4*)&Vs[(k16r * 16 + wn * 8 + j) * 128 + lane * 4];
#pragma unroll
            for (int odd = 0; odd < 2; odd++) {
                int kk8 = k16r * 2 + odd;
                float4 aq[2];
#pragma unroll
                for (int i = 0; i < 2; i++)
                    aq[i] = *(const float4*)&Ss[(kk8 * 8 + wm * 2 + i) * 128 + lane * 4];
#pragma unroll
                for (int i = 0; i < 2; i++) {
                    uint32_t af[4] = { f2u(aq[i].x), f2u(aq[i].y),
                                       f2u(aq[i].z), f2u(aq[i].w) };
#pragma unroll
                    for (int j = 0; j < 8; j++) {
                        uint32_t bf[2];
                        if (odd == 0) { bf[0] = f2u(bq[j].x); bf[1] = f2u(bq[j].y); }
                        else          { bf[0] = f2u(bq[j].z); bf[1] = f2u(bq[j].w); }
                        mma_tf32(oa[i][j], af, bf);
                    }
                }
            }
        }
    }

    __syncthreads();

    // ---- write attn = O / l, rounded (row-major; repacked for O-proj) ----
#pragma unroll
    for (int i = 0; i < 2; i++) {
        int r0 = wm * 32 + i * 16 + g;
        float invl0 = 1.0f / lrow[r0];
        float invl1 = 1.0f / lrow[r0 + 8];
        size_t row0 = (size_t)(b * SEQ + q0 + r0) * DIM + h * HDIM;
        size_t row1 = row0 + (size_t)8 * DIM;
#pragma unroll
        for (int j = 0; j < 8; j++) {
            int c = wn * 64 + j * 8 + tig * 2;
            *(float2*)&g_attn[row0 + c] =
                make_float2(rtf32(oa[i][j][0] * invl0), rtf32(oa[i][j][1] * invl0));
            *(float2*)&g_attn[row1 + c] =
                make_float2(rtf32(oa[i][j][2] * invl1), rtf32(oa[i][j][3] * invl1));
        }
    }
}

// ============================================================================
extern "C" void kernel_launch(void* const* d_in, const int* in_sizes, int n_in,
                              void* d_out, int out_size)
{
    const float* x        = (const float*)d_in[0];
    const int*   seq_lens = (const int*)d_in[1];
    /* d_in[2] grid_sizes (int64) — unused by reference */
    const float* freqs    = (const float*)d_in[3];
    const float* Wq       = (const float*)d_in[4];
    const float* Wk       = (const float*)d_in[5];
    const float* Wv       = (const float*)d_in[6];
    const float* Wo       = (const float*)d_in[7];
    const float* bo       = (const float*)d_in[8];
    const float* gq       = (const float*)d_in[9];
    const float* gk       = (const float*)d_in[10];
    float* out = (float*)d_out;

    cudaFuncSetAttribute((const void*)gemm_mma_tf32<false, false>,
                         cudaFuncAttributeMaxDynamicSharedMemorySize, GEMM_SMEM_BYTES);
    cudaFuncSetAttribute((const void*)gemm_mma_tf32<false, true>,
                         cudaFuncAttributeMaxDynamicSharedMemorySize, GEMM_SMEM_BYTES);
    cudaFuncSetAttribute((const void*)gemm_mma_tf32<true, false>,
                         cudaFuncAttributeMaxDynamicSharedMemorySize, GEMM_SMEM_BYTES);
    cudaFuncSetAttribute((const void*)attn_kernel,
                         cudaFuncAttributeMaxDynamicSharedMemorySize, ATTN_SMEM_BYTES);

    float *pq, *pk, *pv, *pa, *pxr, *pqp, *pwr;
    cudaGetSymbolAddress((void**)&pq,  g_q);
    cudaGetSymbolAddress((void**)&pk,  g_k);
    cudaGetSymbolAddress((void**)&pv,  g_v);
    cudaGetSymbolAddress((void**)&pa,  g_attn);
    cudaGetSymbolAddress((void**)&pxr, g_xr);
    cudaGetSymbolAddress((void**)&pqp, g_qp);
    cudaGetSymbolAddress((void**)&pwr, g_wr4);

    const dim3 ggrid(DIM / 128, MROWS / 128);     // (16, 32)
    const size_t WSZ = (size_t)DIM * DIM;

    // fragment-pack (+ tf32-round) x and weights
    repack_a_kernel<<<dim3(DIM / 32, MROWS / 64), 256>>>(x, pxr);
    repack_b4_kernel<<<dim3(DIM / 32, DIM / 64, 4), 256>>>(Wq, Wk, Wv, Wo, pwr);

    gemm_mma_tf32<false, false><<<ggrid, 128, GEMM_SMEM_BYTES>>>(pxr, pwr,           pq, nullptr);
    gemm_mma_tf32<false, false><<<ggrid, 128, GEMM_SMEM_BYTES>>>(pxr, pwr + WSZ,     pk, nullptr);
    gemm_mma_tf32<false, true ><<<ggrid, 128, GEMM_SMEM_BYTES>>>(pxr, pwr + 2 * WSZ, pv, nullptr); // V packed

    // rmsnorm+rope: q -> packed A-frag (g_qp), k -> packed B-frag (g_xr)
    rmsnorm_rope_kernel<<<dim3(MROWS, 2), 256>>>(pq, pk, pqp, pxr, gq, gk, freqs);

    attn_kernel<<<dim3(SEQ / BLKQ, HEADS, BATCH), 256, ATTN_SMEM_BYTES>>>(
        seq_lens, pqp, pxr, pv);

    // repack attention output for the O-projection (g_xr free after attention)
    repack_a_kernel<<<dim3(DIM / 32, MROWS / 64), 256>>>(pa, pxr);

    gemm_mma_tf32<true, false><<<ggrid, 128, GEMM_SMEM_BYTES>>>(pxr, pwr + 3 * WSZ, out, bo);
}